// round 1
// baseline (speedup 1.0000x reference)
#include <cuda_runtime.h>
#include <cuda_bf16.h>

// Problem: B=8, N=2048, L=1280, H=160
//   q = x@Wq^T+bq [B,N,H]; k = x@Wk^T+bk; v = x@Wv^T+bv [B,N,L]
//   E = q@k^T [B,N,N]; A = softmax(E); out = A@v + x
//
// Round 1: fp32 SIMT baseline. Staged GEMMs + softmax, scratch in device globals.

#define BM 128
#define BN 128
#define BK 16
#define TM 8
#define TN 8
#define NTHR 256

// Scratch (allocation-free per harness rules): ~240 MB total.
__device__ float g_q[8 * 2048 * 160];    // 10.5 MB
__device__ float g_k[8 * 2048 * 160];    // 10.5 MB
__device__ float g_v[8 * 2048 * 1280];   // 83.9 MB
__device__ float g_e[8 * 2048 * 2048];   // 134.2 MB

// C = A @ op(B) + bias + resid
//   BT=true : B is [Nn,K] row-major (C = A B^T)
//   BT=false: B is [K,Nn] row-major (C = A B)
// A [M,K] row-major. Batched via blockIdx.z with strides sA/sB/sC (resid uses sC).
template <bool BT>
__global__ __launch_bounds__(NTHR, 2)
void gemm_kernel(const float* __restrict__ A, const float* __restrict__ B,
                 float* __restrict__ C, const float* __restrict__ bias,
                 const float* __restrict__ resid,
                 int M, int Nn, int K, int lda, int ldb, int ldc,
                 long long sA, long long sB, long long sC)
{
    __shared__ float As[2][BK][BM];
    __shared__ float Bs[2][BK][BN];

    A += (long long)blockIdx.z * sA;
    B += (long long)blockIdx.z * sB;
    C += (long long)blockIdx.z * sC;
    if (resid) resid += (long long)blockIdx.z * sC;

    const int tid  = threadIdx.x;
    const int row0 = blockIdx.y * BM;
    const int col0 = blockIdx.x * BN;

    float4 aR[2], bR[2];

    auto ldgA = [&](int kt) {
        #pragma unroll
        for (int i = 0; i < 2; i++) {
            int m  = (tid >> 2) + i * 64;
            int r  = row0 + m;
            int kk = kt * BK + (tid & 3) * 4;
            aR[i] = (r < M) ? *(const float4*)(A + (long long)r * lda + kk)
                            : make_float4(0.f, 0.f, 0.f, 0.f);
        }
    };
    auto ldgB = [&](int kt) {
        if (BT) {
            #pragma unroll
            for (int i = 0; i < 2; i++) {
                int n  = (tid >> 2) + i * 64;
                int c  = col0 + n;
                int kk = kt * BK + (tid & 3) * 4;
                bR[i] = (c < Nn) ? *(const float4*)(B + (long long)c * ldb + kk)
                                 : make_float4(0.f, 0.f, 0.f, 0.f);
            }
        } else {
            #pragma unroll
            for (int i = 0; i < 2; i++) {
                int kk = kt * BK + (tid >> 5) + i * 8;
                int c  = col0 + (tid & 31) * 4;
                bR[i] = (c < Nn) ? *(const float4*)(B + (long long)kk * ldb + c)
                                 : make_float4(0.f, 0.f, 0.f, 0.f);
            }
        }
    };
    auto stsA = [&](int buf) {
        #pragma unroll
        for (int i = 0; i < 2; i++) {
            int m  = (tid >> 2) + i * 64;
            int kk = (tid & 3) * 4;
            As[buf][kk + 0][m] = aR[i].x;
            As[buf][kk + 1][m] = aR[i].y;
            As[buf][kk + 2][m] = aR[i].z;
            As[buf][kk + 3][m] = aR[i].w;
        }
    };
    auto stsB = [&](int buf) {
        if (BT) {
            #pragma unroll
            for (int i = 0; i < 2; i++) {
                int n  = (tid >> 2) + i * 64;
                int kk = (tid & 3) * 4;
                Bs[buf][kk + 0][n] = bR[i].x;
                Bs[buf][kk + 1][n] = bR[i].y;
                Bs[buf][kk + 2][n] = bR[i].z;
                Bs[buf][kk + 3][n] = bR[i].w;
            }
        } else {
            #pragma unroll
            for (int i = 0; i < 2; i++) {
                int kk = (tid >> 5) + i * 8;
                int n  = (tid & 31) * 4;
                *(float4*)&Bs[buf][kk][n] = bR[i];
            }
        }
    };

    float acc[TM][TN];
    #pragma unroll
    for (int i = 0; i < TM; i++)
        #pragma unroll
        for (int j = 0; j < TN; j++) acc[i][j] = 0.f;

    const int nk = K / BK;  // all K here are multiples of 16
    ldgA(0); ldgB(0);
    stsA(0); stsB(0);
    __syncthreads();

    const int my = (tid >> 4) * TM;
    const int nx = (tid & 15) * TN;

    for (int t = 0; t < nk; t++) {
        const int cur = t & 1;
        if (t + 1 < nk) { ldgA(t + 1); ldgB(t + 1); }
        #pragma unroll
        for (int k = 0; k < BK; k++) {
            float a[TM], bb[TN];
            *(float4*)&a[0]  = *(const float4*)&As[cur][k][my];
            *(float4*)&a[4]  = *(const float4*)&As[cur][k][my + 4];
            *(float4*)&bb[0] = *(const float4*)&Bs[cur][k][nx];
            *(float4*)&bb[4] = *(const float4*)&Bs[cur][k][nx + 4];
            #pragma unroll
            for (int i = 0; i < TM; i++)
                #pragma unroll
                for (int j = 0; j < TN; j++)
                    acc[i][j] = fmaf(a[i], bb[j], acc[i][j]);
        }
        if (t + 1 < nk) { stsA(cur ^ 1); stsB(cur ^ 1); }
        __syncthreads();
    }

    #pragma unroll
    for (int i = 0; i < TM; i++) {
        int m = row0 + my + i;
        if (m >= M) continue;
        #pragma unroll
        for (int j = 0; j < TN; j++) {
            int n = col0 + nx + j;
            if (n >= Nn) continue;
            float val = acc[i][j];
            if (bias)  val += bias[n];
            if (resid) val += resid[(long long)m * ldc + n];
            C[(long long)m * ldc + n] = val;
        }
    }
}

// Row softmax over 2048 columns; one 256-thread block per row.
__global__ __launch_bounds__(256)
void softmax_kernel(float* __restrict__ E)
{
    const int n = 2048;
    float* p = E + (long long)blockIdx.x * n;
    const int tid = threadIdx.x;

    float4 v0 = *(float4*)(p + tid * 4);
    float4 v1 = *(float4*)(p + 1024 + tid * 4);

    float m = fmaxf(fmaxf(fmaxf(v0.x, v0.y), fmaxf(v0.z, v0.w)),
                    fmaxf(fmaxf(v1.x, v1.y), fmaxf(v1.z, v1.w)));
    #pragma unroll
    for (int o = 16; o > 0; o >>= 1) m = fmaxf(m, __shfl_xor_sync(0xffffffffu, m, o));

    __shared__ float rmax[8], rsum[8];
    if ((tid & 31) == 0) rmax[tid >> 5] = m;
    __syncthreads();
    float rowmax = rmax[0];
    #pragma unroll
    for (int i = 1; i < 8; i++) rowmax = fmaxf(rowmax, rmax[i]);

    v0.x = __expf(v0.x - rowmax); v0.y = __expf(v0.y - rowmax);
    v0.z = __expf(v0.z - rowmax); v0.w = __expf(v0.w - rowmax);
    v1.x = __expf(v1.x - rowmax); v1.y = __expf(v1.y - rowmax);
    v1.z = __expf(v1.z - rowmax); v1.w = __expf(v1.w - rowmax);

    float s = v0.x + v0.y + v0.z + v0.w + v1.x + v1.y + v1.z + v1.w;
    #pragma unroll
    for (int o = 16; o > 0; o >>= 1) s += __shfl_xor_sync(0xffffffffu, s, o);
    if ((tid & 31) == 0) rsum[tid >> 5] = s;
    __syncthreads();
    float tot = 0.f;
    #pragma unroll
    for (int i = 0; i < 8; i++) tot += rsum[i];

    const float inv = 1.f / tot;
    v0.x *= inv; v0.y *= inv; v0.z *= inv; v0.w *= inv;
    v1.x *= inv; v1.y *= inv; v1.z *= inv; v1.w *= inv;
    *(float4*)(p + tid * 4) = v0;
    *(float4*)(p + 1024 + tid * 4) = v1;
}

extern "C" void kernel_launch(void* const* d_in, const int* in_sizes, int n_in,
                              void* d_out, int out_size)
{
    const float* x  = (const float*)d_in[0];  // [8,2048,1280]
    const float* Wq = (const float*)d_in[1];  // [160,1280]
    const float* bq = (const float*)d_in[2];  // [160]
    const float* Wk = (const float*)d_in[3];  // [160,1280]
    const float* bk = (const float*)d_in[4];  // [160]
    const float* Wv = (const float*)d_in[5];  // [1280,1280]
    const float* bv = (const float*)d_in[6];  // [1280]
    float* out = (float*)d_out;               // [8,2048,1280]

    float *q, *k, *v, *e;
    cudaGetSymbolAddress((void**)&q, g_q);
    cudaGetSymbolAddress((void**)&k, g_k);
    cudaGetSymbolAddress((void**)&v, g_v);
    cudaGetSymbolAddress((void**)&e, g_e);

    const dim3 thr(NTHR);

    // Projections: q/k [16384,160], v [16384,1280]; all NT over K=1280.
    gemm_kernel<true><<<dim3(2, 128, 1), thr>>>(
        x, Wq, q, bq, nullptr, 16384, 160, 1280, 1280, 1280, 160, 0, 0, 0);
    gemm_kernel<true><<<dim3(2, 128, 1), thr>>>(
        x, Wk, k, bk, nullptr, 16384, 160, 1280, 1280, 1280, 160, 0, 0, 0);
    gemm_kernel<true><<<dim3(10, 128, 1), thr>>>(
        x, Wv, v, bv, nullptr, 16384, 1280, 1280, 1280, 1280, 1280, 0, 0, 0);

    // Energy: per batch, E[b] = q[b] @ k[b]^T  (M=N=2048, K=160)
    gemm_kernel<true><<<dim3(16, 16, 8), thr>>>(
        q, k, e, nullptr, nullptr, 2048, 2048, 160, 160, 160, 2048,
        2048LL * 160, 2048LL * 160, 2048LL * 2048);

    // Softmax over rows (8*2048 rows of 2048)
    softmax_kernel<<<8 * 2048, 256>>>(e);

    // out[b] = attn[b] @ v[b] + x[b]  (M=2048, Nn=1280, K=2048)
    gemm_kernel<false><<<dim3(10, 16, 8), thr>>>(
        e, v, out, nullptr, x, 2048, 1280, 2048, 2048, 1280, 1280,
        2048LL * 2048, 2048LL * 1280, 2048LL * 1280);
}

// round 3
// speedup vs baseline: 1.7672x; 1.7672x over previous
#include <cuda_runtime.h>
#include <cuda_bf16.h>
#include <cstdint>

// ============================================================================
// BagSelfAttention: B=8, N=2048, L=1280, H=160
//   q=x@Wq^T+bq; k=x@Wk^T+bk; v=x@Wv^T+bv; E=q k^T; A=softmax(E); out=A v + x
// Round 3: mma.sync (HMMA) bf16 split-precision (hi/lo, 3-term) GEMMs,
//          cp.async 3-stage pipeline. (tcgen05 PTX is rejected at the
//          harness's compute_103 virtual target, so we use arch-neutral PTX.)
// ============================================================================

#define BB   8
#define NN   2048
#define LL   1280
#define HH   160
#define MTOT (BB * NN)       // 16384
#define KQK  192             // padded H (160 -> 192)
#define NWQK 384             // padded stacked Wq|Wk rows (320 -> 384)

// ---------------- scratch (device globals; no allocation allowed) ----------
__device__ __align__(1024) __nv_bfloat16 g_xh [MTOT * LL];
__device__ __align__(1024) __nv_bfloat16 g_xl [MTOT * LL];
__device__ __align__(1024) __nv_bfloat16 g_wqkh[NWQK * LL];
__device__ __align__(1024) __nv_bfloat16 g_wqkl[NWQK * LL];
__device__ __align__(1024) __nv_bfloat16 g_wvh [LL * LL];
__device__ __align__(1024) __nv_bfloat16 g_wvl [LL * LL];
__device__ __align__(1024) __nv_bfloat16 g_qh  [MTOT * KQK];
__device__ __align__(1024) __nv_bfloat16 g_ql  [MTOT * KQK];
__device__ __align__(1024) __nv_bfloat16 g_kh  [MTOT * KQK];
__device__ __align__(1024) __nv_bfloat16 g_kl  [MTOT * KQK];
__device__ __align__(1024) float         g_e   [MTOT * NN];
__device__ __align__(1024) __nv_bfloat16 g_ath [MTOT * NN];
__device__ __align__(1024) __nv_bfloat16 g_atl [MTOT * NN];
__device__ __align__(1024) __nv_bfloat16 g_vth [BB * LL * NN];
__device__ __align__(1024) __nv_bfloat16 g_vtl [BB * LL * NN];
__device__ __align__(1024) float         g_bqk [NWQK];

// ---------------- PTX helpers ----------------
__device__ __forceinline__ uint32_t smem_u32(const void* p) {
    uint32_t a;
    asm("{ .reg .u64 t; cvta.to.shared.u64 t, %1; cvt.u32.u64 %0, t; }"
        : "=r"(a) : "l"(p));
    return a;
}

#define CPA(dst, src) \
    asm volatile("cp.async.cg.shared.global [%0], [%1], 16;" :: "r"(dst), "l"(src) : "memory")
#define CPCOMMIT() asm volatile("cp.async.commit_group;" ::: "memory")
#define CPWAIT1()  asm volatile("cp.async.wait_group 1;" ::: "memory")

#define LDSM4(R, A) \
    asm volatile("ldmatrix.sync.aligned.m8n8.x4.shared.b16 {%0,%1,%2,%3}, [%4];" \
                 : "=r"((R)[0]), "=r"((R)[1]), "=r"((R)[2]), "=r"((R)[3]) : "r"(A))

#define MMA16816(C, A, B0, B1) \
    asm volatile("mma.sync.aligned.m16n8k16.row.col.f32.bf16.bf16.f32 " \
                 "{%0,%1,%2,%3}, {%4,%5,%6,%7}, {%8,%9}, {%0,%1,%2,%3};" \
                 : "+f"((C)[0]), "+f"((C)[1]), "+f"((C)[2]), "+f"((C)[3]) \
                 : "r"((A)[0]), "r"((A)[1]), "r"((A)[2]), "r"((A)[3]), "r"(B0), "r"(B1))

__device__ __forceinline__ void split_store(float v, __nv_bfloat16* h, __nv_bfloat16* l,
                                            long long idx) {
    __nv_bfloat16 hi = __float2bfloat16(v);
    h[idx] = hi;
    l[idx] = __float2bfloat16(v - __bfloat162float(hi));
}

// ---------------- conversion kernels ----------------
__global__ void split_kernel(const float* __restrict__ x,
                             __nv_bfloat16* __restrict__ h,
                             __nv_bfloat16* __restrict__ l, long long n) {
    long long i = ((long long)blockIdx.x * blockDim.x + threadIdx.x) * 4;
    if (i >= n) return;
    float4 v = *(const float4*)(x + i);
    __nv_bfloat162 h0, h1, l0, l1;
    h0.x = __float2bfloat16(v.x); l0.x = __float2bfloat16(v.x - __bfloat162float(h0.x));
    h0.y = __float2bfloat16(v.y); l0.y = __float2bfloat16(v.y - __bfloat162float(h0.y));
    h1.x = __float2bfloat16(v.z); l1.x = __float2bfloat16(v.z - __bfloat162float(h1.x));
    h1.y = __float2bfloat16(v.w); l1.y = __float2bfloat16(v.w - __bfloat162float(h1.y));
    *(__nv_bfloat162*)(h + i) = h0; *(__nv_bfloat162*)(h + i + 2) = h1;
    *(__nv_bfloat162*)(l + i) = l0; *(__nv_bfloat162*)(l + i + 2) = l1;
}

__global__ void build_wqk_kernel(const float* __restrict__ Wq, const float* __restrict__ bq,
                                 const float* __restrict__ Wk, const float* __restrict__ bk,
                                 __nv_bfloat16* __restrict__ wh, __nv_bfloat16* __restrict__ wl,
                                 float* __restrict__ bqk) {
    long long i = (long long)blockIdx.x * blockDim.x + threadIdx.x;
    if (i >= (long long)NWQK * LL) return;
    int r = (int)(i / LL), c = (int)(i % LL);
    float v = (r < HH) ? Wq[r * LL + c] : (r < 2 * HH) ? Wk[(r - HH) * LL + c] : 0.f;
    split_store(v, wh, wl, i);
    if (c == 0) bqk[r] = (r < HH) ? bq[r] : (r < 2 * HH) ? bk[r - HH] : 0.f;
}

// ---------------- softmax (fp32 in, bf16 hi/lo out) ----------------
__global__ __launch_bounds__(256)
void softmax_split_kernel(const float* __restrict__ E,
                          __nv_bfloat16* __restrict__ ah,
                          __nv_bfloat16* __restrict__ al) {
    const long long row = blockIdx.x;
    const float* p = E + row * NN;
    const int tid = threadIdx.x;

    float4 v0 = *(const float4*)(p + tid * 4);
    float4 v1 = *(const float4*)(p + 1024 + tid * 4);

    float m = fmaxf(fmaxf(fmaxf(v0.x, v0.y), fmaxf(v0.z, v0.w)),
                    fmaxf(fmaxf(v1.x, v1.y), fmaxf(v1.z, v1.w)));
    #pragma unroll
    for (int o = 16; o > 0; o >>= 1) m = fmaxf(m, __shfl_xor_sync(0xffffffffu, m, o));

    __shared__ float rmax[8], rsum[8];
    if ((tid & 31) == 0) rmax[tid >> 5] = m;
    __syncthreads();
    float rowmax = rmax[0];
    #pragma unroll
    for (int i = 1; i < 8; i++) rowmax = fmaxf(rowmax, rmax[i]);

    v0.x = __expf(v0.x - rowmax); v0.y = __expf(v0.y - rowmax);
    v0.z = __expf(v0.z - rowmax); v0.w = __expf(v0.w - rowmax);
    v1.x = __expf(v1.x - rowmax); v1.y = __expf(v1.y - rowmax);
    v1.z = __expf(v1.z - rowmax); v1.w = __expf(v1.w - rowmax);

    float s = v0.x + v0.y + v0.z + v0.w + v1.x + v1.y + v1.z + v1.w;
    #pragma unroll
    for (int o = 16; o > 0; o >>= 1) s += __shfl_xor_sync(0xffffffffu, s, o);
    if ((tid & 31) == 0) rsum[tid >> 5] = s;
    __syncthreads();
    float tot = 0.f;
    #pragma unroll
    for (int i = 0; i < 8; i++) tot += rsum[i];

    const float inv = 1.f / tot;
    float vals[8] = {v0.x * inv, v0.y * inv, v0.z * inv, v0.w * inv,
                     v1.x * inv, v1.y * inv, v1.z * inv, v1.w * inv};
    long long base = row * NN;
    #pragma unroll
    for (int j = 0; j < 4; j++) split_store(vals[j], ah, al, base + tid * 4 + j);
    #pragma unroll
    for (int j = 0; j < 4; j++) split_store(vals[4 + j], ah, al, base + 1024 + tid * 4 + j);
}

// ---------------- HMMA split-precision GEMM ----------------
// C[128x128] = sum over K of (Ah+Al)[m,k]*(Bh+Bl)[n,k], 3-term, fp32 accum.
// A: [Ma,K] row-major bf16 (hi/lo); B: [Nb,K] row-major bf16 (hi/lo).
// MODE 0: qk-proj  (bias, split-write q/k)
// MODE 1: v-proj   (bias, transposed split-write vT)
// MODE 2: energy   (fp32 store)
// MODE 3: attn@v   (residual add, fp32 store)
template <int MODE>
__global__ __launch_bounds__(256, 1)
void gemm_mma(const __nv_bfloat16* __restrict__ Ah, const __nv_bfloat16* __restrict__ Al,
              int lda, long long sA,
              const __nv_bfloat16* __restrict__ Bh, const __nv_bfloat16* __restrict__ Bl,
              int ldb, long long sB,
              float* __restrict__ fout, const float* __restrict__ bias,
              const float* __restrict__ resid,
              __nv_bfloat16* __restrict__ o0, __nv_bfloat16* __restrict__ o1,
              __nv_bfloat16* __restrict__ o2, __nv_bfloat16* __restrict__ o3,
              int K)
{
    extern __shared__ char smem[];
    constexpr int TSZ = 128 * 32 * 2;      // 8 KB per operand tile
    constexpr int SSZ = 4 * TSZ;           // 32 KB per stage
    const uint32_t sb0 = smem_u32(smem);

    const int tid = threadIdx.x, lane = tid & 31, wid = tid >> 5;
    const int bz = blockIdx.z;
    const int m0 = blockIdx.y * 128;
    const int n0 = blockIdx.x * 128;

    Ah += bz * sA; Al += bz * sA;
    Bh += bz * sB; Bl += bz * sB;

    // per-thread cp.async source row/chunk (2 chunks of 16B per operand tile)
    auto load_stage = [&](int kt, int s) {
        const uint32_t sb = sb0 + (uint32_t)s * SSZ;
        const int k0 = kt * 32;
        #pragma unroll
        for (int i = 0; i < 2; i++) {
            int c   = tid + i * 256;
            int row = c >> 2, ch = c & 3;
            uint32_t off = row * 64 + ((ch ^ ((row >> 1) & 3)) << 4);
            const __nv_bfloat16* a = Ah + (long long)(m0 + row) * lda + k0 + ch * 8;
            const __nv_bfloat16* al = Al + (long long)(m0 + row) * lda + k0 + ch * 8;
            const __nv_bfloat16* b = Bh + (long long)(n0 + row) * ldb + k0 + ch * 8;
            const __nv_bfloat16* bl = Bl + (long long)(n0 + row) * ldb + k0 + ch * 8;
            CPA(sb + off, a);
            CPA(sb + TSZ + off, al);
            CPA(sb + 2 * TSZ + off, b);
            CPA(sb + 3 * TSZ + off, bl);
        }
        CPCOMMIT();
    };

    const int nk = K / 32;
    load_stage(0, 0);
    load_stage(1, 1);

    const int wm = (wid >> 2) * 64;   // warp M offset (2 warps)
    const int wn = (wid & 3) * 32;    // warp N offset (4 warps)

    float acc[4][4][4];
    #pragma unroll
    for (int i = 0; i < 4; i++)
        #pragma unroll
        for (int j = 0; j < 4; j++)
            #pragma unroll
            for (int r = 0; r < 4; r++) acc[i][j][r] = 0.f;

    for (int t = 0; t < nk; t++) {
        const int s = t % 3;
        CPWAIT1();
        __syncthreads();
        if (t + 2 < nk) load_stage(t + 2, (t + 2) % 3);
        else CPCOMMIT();

        const uint32_t sb = sb0 + (uint32_t)s * SSZ;
        #pragma unroll
        for (int ks = 0; ks < 2; ks++) {
            uint32_t ah[4][4], alr[4][4];
            #pragma unroll
            for (int i = 0; i < 4; i++) {
                int row = wm + i * 16 + (lane & 7) + (lane & 8);
                int cc  = ks * 2 + (lane >> 4);
                uint32_t adr = sb + row * 64 + ((cc ^ ((row >> 1) & 3)) << 4);
                LDSM4(ah[i], adr);
                LDSM4(alr[i], adr + TSZ);
            }
            uint32_t bh[4][2], blr[4][2];
            #pragma unroll
            for (int j2 = 0; j2 < 2; j2++) {
                int row = wn + j2 * 16 + (lane & 7) + ((lane & 16) >> 1);
                int cc  = ks * 2 + ((lane >> 3) & 1);
                uint32_t adr = sb + 2 * TSZ + row * 64 + ((cc ^ ((row >> 1) & 3)) << 4);
                uint32_t r[4];
                LDSM4(r, adr);
                bh[2 * j2][0] = r[0]; bh[2 * j2][1] = r[1];
                bh[2 * j2 + 1][0] = r[2]; bh[2 * j2 + 1][1] = r[3];
                LDSM4(r, adr + TSZ);
                blr[2 * j2][0] = r[0]; blr[2 * j2][1] = r[1];
                blr[2 * j2 + 1][0] = r[2]; blr[2 * j2 + 1][1] = r[3];
            }
            #pragma unroll
            for (int i = 0; i < 4; i++)
                #pragma unroll
                for (int j = 0; j < 4; j++) {
                    MMA16816(acc[i][j], ah[i], bh[j][0], bh[j][1]);
                    MMA16816(acc[i][j], ah[i], blr[j][0], blr[j][1]);
                    MMA16816(acc[i][j], alr[i], bh[j][0], bh[j][1]);
                }
        }
        __syncthreads();
    }

    // ---------------- epilogue ----------------
    const int g = lane >> 2, t4 = lane & 3;
    #pragma unroll
    for (int i = 0; i < 4; i++) {
        #pragma unroll
        for (int j = 0; j < 4; j++) {
            #pragma unroll
            for (int half = 0; half < 2; half++) {
                const int m = m0 + wm + i * 16 + g + half * 8;    // local row
                const int n = n0 + wn + j * 8 + t4 * 2;           // local col
                float v0 = acc[i][j][half * 2 + 0];
                float v1 = acc[i][j][half * 2 + 1];
                if (MODE == 2) {
                    float2* dst = (float2*)(fout + (long long)bz * NN * NN +
                                            (long long)m * NN + n);
                    *dst = make_float2(v0, v1);
                } else if (MODE == 3) {
                    const long long off = (long long)bz * NN * LL + (long long)m * LL + n;
                    float2 rx = *(const float2*)(resid + off);
                    *(float2*)(fout + off) = make_float2(v0 + rx.x, v1 + rx.y);
                } else if (MODE == 1) {
                    const int b = m >> 11, ii = m & (NN - 1);
                    float a0 = v0 + bias[n], a1 = v1 + bias[n + 1];
                    long long i0 = (((long long)(b * LL + n)) << 11) + ii;
                    long long i1 = (((long long)(b * LL + n + 1)) << 11) + ii;
                    split_store(a0, o0, o1, i0);
                    split_store(a1, o0, o1, i1);
                } else {  // MODE 0
                    #pragma unroll
                    for (int e = 0; e < 2; e++) {
                        int nn = n + e;
                        float val = (e ? v1 : v0) + bias[nn];
                        if (nn < HH)
                            split_store(val, o0, o1, (long long)m * KQK + nn);
                        else if (nn < 2 * HH)
                            split_store(val, o2, o3, (long long)m * KQK + (nn - HH));
                    }
                }
            }
        }
    }
}

// ---------------- host side ----------------
extern "C" void kernel_launch(void* const* d_in, const int* in_sizes, int n_in,
                              void* d_out, int out_size) {
    const float* x  = (const float*)d_in[0];
    const float* Wq = (const float*)d_in[1];
    const float* bq = (const float*)d_in[2];
    const float* Wk = (const float*)d_in[3];
    const float* bk = (const float*)d_in[4];
    const float* Wv = (const float*)d_in[5];
    const float* bv = (const float*)d_in[6];
    float* out = (float*)d_out;

    __nv_bfloat16 *xh, *xl, *wqkh, *wqkl, *wvh, *wvl, *qh, *ql, *kh, *kl, *ath, *atl, *vth, *vtl;
    float *e, *bqk;
    cudaGetSymbolAddress((void**)&xh, g_xh);     cudaGetSymbolAddress((void**)&xl, g_xl);
    cudaGetSymbolAddress((void**)&wqkh, g_wqkh); cudaGetSymbolAddress((void**)&wqkl, g_wqkl);
    cudaGetSymbolAddress((void**)&wvh, g_wvh);   cudaGetSymbolAddress((void**)&wvl, g_wvl);
    cudaGetSymbolAddress((void**)&qh, g_qh);     cudaGetSymbolAddress((void**)&ql, g_ql);
    cudaGetSymbolAddress((void**)&kh, g_kh);     cudaGetSymbolAddress((void**)&kl, g_kl);
    cudaGetSymbolAddress((void**)&e, g_e);
    cudaGetSymbolAddress((void**)&ath, g_ath);   cudaGetSymbolAddress((void**)&atl, g_atl);
    cudaGetSymbolAddress((void**)&vth, g_vth);   cudaGetSymbolAddress((void**)&vtl, g_vtl);
    cudaGetSymbolAddress((void**)&bqk, g_bqk);

    constexpr int SMEM = 3 * 4 * 128 * 32 * 2;  // 98304
    static bool attr_done = false;
    if (!attr_done) {
        cudaFuncSetAttribute(gemm_mma<0>, cudaFuncAttributeMaxDynamicSharedMemorySize, SMEM);
        cudaFuncSetAttribute(gemm_mma<1>, cudaFuncAttributeMaxDynamicSharedMemorySize, SMEM);
        cudaFuncSetAttribute(gemm_mma<2>, cudaFuncAttributeMaxDynamicSharedMemorySize, SMEM);
        cudaFuncSetAttribute(gemm_mma<3>, cudaFuncAttributeMaxDynamicSharedMemorySize, SMEM);
        attr_done = true;
    }

    // 1) conversions
    {
        long long n = (long long)MTOT * LL;
        split_kernel<<<(unsigned)(n / 4 / 256), 256>>>(x, xh, xl, n);
    }
    build_wqk_kernel<<<(NWQK * LL + 255) / 256, 256>>>(Wq, bq, Wk, bk, wqkh, wqkl, bqk);
    {
        long long n = (long long)LL * LL;
        split_kernel<<<(unsigned)((n / 4 + 255) / 256), 256>>>(Wv, wvh, wvl, n);
    }
    size_t qkb = (size_t)MTOT * KQK * sizeof(__nv_bfloat16);
    cudaMemsetAsync(qh, 0, qkb); cudaMemsetAsync(ql, 0, qkb);
    cudaMemsetAsync(kh, 0, qkb); cudaMemsetAsync(kl, 0, qkb);

    // 2) qk projection: [16384, 384] = x @ Wqk^T -> split-write q/k (K=1280)
    gemm_mma<0><<<dim3(NWQK / 128, MTOT / 128, 1), 256, SMEM>>>(
        xh, xl, LL, 0, wqkh, wqkl, LL, 0,
        nullptr, bqk, nullptr, qh, ql, kh, kl, LL);

    // 3) v projection: [16384, 1280] = x @ Wv^T -> transposed split-write vT
    gemm_mma<1><<<dim3(LL / 128, MTOT / 128, 1), 256, SMEM>>>(
        xh, xl, LL, 0, wvh, wvl, LL, 0,
        nullptr, bv, nullptr, vth, vtl, nullptr, nullptr, LL);

    // 4) energy: per batch E = q @ k^T (K = 192 padded)
    gemm_mma<2><<<dim3(NN / 128, NN / 128, BB), 256, SMEM>>>(
        qh, ql, KQK, (long long)NN * KQK, kh, kl, KQK, (long long)NN * KQK,
        e, nullptr, nullptr, nullptr, nullptr, nullptr, nullptr, KQK);

    // 5) softmax + split
    softmax_split_kernel<<<MTOT, 256>>>(e, ath, atl);

    // 6) attn @ v + residual (K = 2048)
    gemm_mma<3><<<dim3(LL / 128, NN / 128, BB), 256, SMEM>>>(
        ath, atl, NN, (long long)NN * NN, vth, vtl, NN, (long long)LL * NN,
        out, nullptr, x, nullptr, nullptr, nullptr, nullptr, NN);
}

// round 4
// speedup vs baseline: 3.1318x; 1.7722x over previous
#include <cuda_runtime.h>
#include <cuda_bf16.h>
#include <cstdint>

// ============================================================================
// BagSelfAttention: B=8, N=2048, L=1280, H=160
// Round 4: HMMA split-precision GEMMs, 2 CTAs/SM (128-reg diet, phased
//          fragment loading), cp.async 3-stage pipeline.
// ============================================================================

#define BB   8
#define NN   2048
#define LL   1280
#define HH   160
#define MTOT (BB * NN)
#define KQK  192
#define NWQK 384

__device__ __align__(1024) __nv_bfloat16 g_xh [MTOT * LL];
__device__ __align__(1024) __nv_bfloat16 g_xl [MTOT * LL];
__device__ __align__(1024) __nv_bfloat16 g_wqkh[NWQK * LL];
__device__ __align__(1024) __nv_bfloat16 g_wqkl[NWQK * LL];
__device__ __align__(1024) __nv_bfloat16 g_wvh [LL * LL];
__device__ __align__(1024) __nv_bfloat16 g_wvl [LL * LL];
__device__ __align__(1024) __nv_bfloat16 g_qh  [MTOT * KQK];
__device__ __align__(1024) __nv_bfloat16 g_ql  [MTOT * KQK];
__device__ __align__(1024) __nv_bfloat16 g_kh  [MTOT * KQK];
__device__ __align__(1024) __nv_bfloat16 g_kl  [MTOT * KQK];
__device__ __align__(1024) float         g_e   [MTOT * NN];
__device__ __align__(1024) __nv_bfloat16 g_ath [MTOT * NN];
__device__ __align__(1024) __nv_bfloat16 g_atl [MTOT * NN];
__device__ __align__(1024) __nv_bfloat16 g_vth [BB * LL * NN];
__device__ __align__(1024) __nv_bfloat16 g_vtl [BB * LL * NN];
__device__ __align__(1024) float         g_bqk [NWQK];

__device__ __forceinline__ uint32_t smem_u32(const void* p) {
    uint32_t a;
    asm("{ .reg .u64 t; cvta.to.shared.u64 t, %1; cvt.u32.u64 %0, t; }"
        : "=r"(a) : "l"(p));
    return a;
}

#define CPA(dst, src) \
    asm volatile("cp.async.cg.shared.global [%0], [%1], 16;" :: "r"(dst), "l"(src) : "memory")
#define CPCOMMIT() asm volatile("cp.async.commit_group;" ::: "memory")
#define CPWAIT1()  asm volatile("cp.async.wait_group 1;" ::: "memory")

#define LDSM4(R, A) \
    asm volatile("ldmatrix.sync.aligned.m8n8.x4.shared.b16 {%0,%1,%2,%3}, [%4];" \
                 : "=r"((R)[0]), "=r"((R)[1]), "=r"((R)[2]), "=r"((R)[3]) : "r"(A))

#define MMA16816(C, A, B0, B1) \
    asm volatile("mma.sync.aligned.m16n8k16.row.col.f32.bf16.bf16.f32 " \
                 "{%0,%1,%2,%3}, {%4,%5,%6,%7}, {%8,%9}, {%0,%1,%2,%3};" \
                 : "+f"((C)[0]), "+f"((C)[1]), "+f"((C)[2]), "+f"((C)[3]) \
                 : "r"((A)[0]), "r"((A)[1]), "r"((A)[2]), "r"((A)[3]), "r"(B0), "r"(B1))

__device__ __forceinline__ void split_store(float v, __nv_bfloat16* h, __nv_bfloat16* l,
                                            long long idx) {
    __nv_bfloat16 hi = __float2bfloat16(v);
    h[idx] = hi;
    l[idx] = __float2bfloat16(v - __bfloat162float(hi));
}

// ---------------- conversion kernels ----------------
__global__ void split_kernel(const float* __restrict__ x,
                             __nv_bfloat16* __restrict__ h,
                             __nv_bfloat16* __restrict__ l, long long n) {
    long long i = ((long long)blockIdx.x * blockDim.x + threadIdx.x) * 4;
    if (i >= n) return;
    float4 v = *(const float4*)(x + i);
    __nv_bfloat162 h0, h1, l0, l1;
    h0.x = __float2bfloat16(v.x); l0.x = __float2bfloat16(v.x - __bfloat162float(h0.x));
    h0.y = __float2bfloat16(v.y); l0.y = __float2bfloat16(v.y - __bfloat162float(h0.y));
    h1.x = __float2bfloat16(v.z); l1.x = __float2bfloat16(v.z - __bfloat162float(h1.x));
    h1.y = __float2bfloat16(v.w); l1.y = __float2bfloat16(v.w - __bfloat162float(h1.y));
    *(__nv_bfloat162*)(h + i) = h0; *(__nv_bfloat162*)(h + i + 2) = h1;
    *(__nv_bfloat162*)(l + i) = l0; *(__nv_bfloat162*)(l + i + 2) = l1;
}

__global__ void build_wqk_kernel(const float* __restrict__ Wq, const float* __restrict__ bq,
                                 const float* __restrict__ Wk, const float* __restrict__ bk,
                                 __nv_bfloat16* __restrict__ wh, __nv_bfloat16* __restrict__ wl,
                                 float* __restrict__ bqk) {
    long long i = (long long)blockIdx.x * blockDim.x + threadIdx.x;
    if (i >= (long long)NWQK * LL) return;
    int r = (int)(i / LL), c = (int)(i % LL);
    float v = (r < HH) ? Wq[r * LL + c] : (r < 2 * HH) ? Wk[(r - HH) * LL + c] : 0.f;
    split_store(v, wh, wl, i);
    if (c == 0) bqk[r] = (r < HH) ? bq[r] : (r < 2 * HH) ? bk[r - HH] : 0.f;
}

// ---------------- softmax ----------------
__global__ __launch_bounds__(256)
void softmax_split_kernel(const float* __restrict__ E,
                          __nv_bfloat16* __restrict__ ah,
                          __nv_bfloat16* __restrict__ al) {
    const long long row = blockIdx.x;
    const float* p = E + row * NN;
    const int tid = threadIdx.x;

    float4 v0 = *(const float4*)(p + tid * 4);
    float4 v1 = *(const float4*)(p + 1024 + tid * 4);

    float m = fmaxf(fmaxf(fmaxf(v0.x, v0.y), fmaxf(v0.z, v0.w)),
                    fmaxf(fmaxf(v1.x, v1.y), fmaxf(v1.z, v1.w)));
    #pragma unroll
    for (int o = 16; o > 0; o >>= 1) m = fmaxf(m, __shfl_xor_sync(0xffffffffu, m, o));

    __shared__ float rmax[8], rsum[8];
    if ((tid & 31) == 0) rmax[tid >> 5] = m;
    __syncthreads();
    float rowmax = rmax[0];
    #pragma unroll
    for (int i = 1; i < 8; i++) rowmax = fmaxf(rowmax, rmax[i]);

    v0.x = __expf(v0.x - rowmax); v0.y = __expf(v0.y - rowmax);
    v0.z = __expf(v0.z - rowmax); v0.w = __expf(v0.w - rowmax);
    v1.x = __expf(v1.x - rowmax); v1.y = __expf(v1.y - rowmax);
    v1.z = __expf(v1.z - rowmax); v1.w = __expf(v1.w - rowmax);

    float s = v0.x + v0.y + v0.z + v0.w + v1.x + v1.y + v1.z + v1.w;
    #pragma unroll
    for (int o = 16; o > 0; o >>= 1) s += __shfl_xor_sync(0xffffffffu, s, o);
    if ((tid & 31) == 0) rsum[tid >> 5] = s;
    __syncthreads();
    float tot = 0.f;
    #pragma unroll
    for (int i = 0; i < 8; i++) tot += rsum[i];

    const float inv = 1.f / tot;
    float vals[8] = {v0.x * inv, v0.y * inv, v0.z * inv, v0.w * inv,
                     v1.x * inv, v1.y * inv, v1.z * inv, v1.w * inv};
    long long base = row * NN;
    #pragma unroll
    for (int j = 0; j < 4; j++) split_store(vals[j], ah, al, base + tid * 4 + j);
    #pragma unroll
    for (int j = 0; j < 4; j++) split_store(vals[4 + j], ah, al, base + 1024 + tid * 4 + j);
}

// ---------------- HMMA split-precision GEMM (2 CTAs/SM) ----------------
template <int MODE>
__global__ __launch_bounds__(256, 2)
void gemm_mma(const __nv_bfloat16* __restrict__ Ah, const __nv_bfloat16* __restrict__ Al,
              int lda, long long sA,
              const __nv_bfloat16* __restrict__ Bh, const __nv_bfloat16* __restrict__ Bl,
              int ldb, long long sB,
              float* __restrict__ fout, const float* __restrict__ bias,
              const float* __restrict__ resid,
              __nv_bfloat16* __restrict__ o0, __nv_bfloat16* __restrict__ o1,
              __nv_bfloat16* __restrict__ o2, __nv_bfloat16* __restrict__ o3,
              int K)
{
    extern __shared__ char smem[];
    constexpr int TSZ = 128 * 32 * 2;      // 8 KB per operand tile
    constexpr int SSZ = 4 * TSZ;           // 32 KB per stage
    const uint32_t sb0 = smem_u32(smem);

    const int tid = threadIdx.x, lane = tid & 31, wid = tid >> 5;
    const int bz = blockIdx.z;
    const int m0 = blockIdx.y * 128;
    const int n0 = blockIdx.x * 128;

    Ah += bz * sA; Al += bz * sA;
    Bh += bz * sB; Bl += bz * sB;

    auto load_stage = [&](int kt, int s) {
        const uint32_t sb = sb0 + (uint32_t)s * SSZ;
        const int k0 = kt * 32;
        #pragma unroll
        for (int i = 0; i < 2; i++) {
            int c   = tid + i * 256;
            int row = c >> 2, ch = c & 3;
            uint32_t off = row * 64 + ((ch ^ ((row >> 1) & 3)) << 4);
            const __nv_bfloat16* a  = Ah + (long long)(m0 + row) * lda + k0 + ch * 8;
            const __nv_bfloat16* al = Al + (long long)(m0 + row) * lda + k0 + ch * 8;
            const __nv_bfloat16* b  = Bh + (long long)(n0 + row) * ldb + k0 + ch * 8;
            const __nv_bfloat16* bl = Bl + (long long)(n0 + row) * ldb + k0 + ch * 8;
            CPA(sb + off, a);
            CPA(sb + TSZ + off, al);
            CPA(sb + 2 * TSZ + off, b);
            CPA(sb + 3 * TSZ + off, bl);
        }
        CPCOMMIT();
    };

    const int nk = K / 32;
    load_stage(0, 0);
    load_stage(1, 1);

    const int wm = (wid >> 2) * 64;
    const int wn = (wid & 3) * 32;

    float acc[4][4][4];
    #pragma unroll
    for (int i = 0; i < 4; i++)
        #pragma unroll
        for (int j = 0; j < 4; j++)
            #pragma unroll
            for (int r = 0; r < 4; r++) acc[i][j][r] = 0.f;

    // precompute ldmatrix base offsets (per-thread, loop-invariant)
    const int arow = wm + (lane & 7) + (lane & 8);
    const int brow = wn + (lane & 7) + ((lane & 16) >> 1);
    const int acc_k = (lane >> 4);          // A: column selector base
    const int bcc_k = ((lane >> 3) & 1);    // B: column selector base

    for (int t = 0; t < nk; t++) {
        const int s = t % 3;
        CPWAIT1();
        __syncthreads();
        if (t + 2 < nk) load_stage(t + 2, (t + 2) % 3);
        else CPCOMMIT();

        const uint32_t sb = sb0 + (uint32_t)s * SSZ;
        #pragma unroll
        for (int ks = 0; ks < 2; ks++) {
            // ---- phase 1: A-hi + B-hi, main term ----
            uint32_t ah[4][4];
            #pragma unroll
            for (int i = 0; i < 4; i++) {
                int row = arow + i * 16;
                int cc  = ks * 2 + acc_k;
                LDSM4(ah[i], sb + row * 64 + ((cc ^ ((row >> 1) & 3)) << 4));
            }
            uint32_t bh[4][2];
            #pragma unroll
            for (int j2 = 0; j2 < 2; j2++) {
                int row = brow + j2 * 16;
                int cc  = ks * 2 + bcc_k;
                uint32_t r[4];
                LDSM4(r, sb + 2 * TSZ + row * 64 + ((cc ^ ((row >> 1) & 3)) << 4));
                bh[2 * j2][0] = r[0]; bh[2 * j2][1] = r[1];
                bh[2 * j2 + 1][0] = r[2]; bh[2 * j2 + 1][1] = r[3];
            }
            #pragma unroll
            for (int i = 0; i < 4; i++)
                #pragma unroll
                for (int j = 0; j < 4; j++)
                    MMA16816(acc[i][j], ah[i], bh[j][0], bh[j][1]);

            // ---- phase 2: A-hi x B-lo ----
            {
                uint32_t bl[4][2];
                #pragma unroll
                for (int j2 = 0; j2 < 2; j2++) {
                    int row = brow + j2 * 16;
                    int cc  = ks * 2 + bcc_k;
                    uint32_t r[4];
                    LDSM4(r, sb + 3 * TSZ + row * 64 + ((cc ^ ((row >> 1) & 3)) << 4));
                    bl[2 * j2][0] = r[0]; bl[2 * j2][1] = r[1];
                    bl[2 * j2 + 1][0] = r[2]; bl[2 * j2 + 1][1] = r[3];
                }
                #pragma unroll
                for (int i = 0; i < 4; i++)
                    #pragma unroll
                    for (int j = 0; j < 4; j++)
                        MMA16816(acc[i][j], ah[i], bl[j][0], bl[j][1]);
            }

            // ---- phase 3: A-lo x B-hi (reuse ah regs for al) ----
            #pragma unroll
            for (int i = 0; i < 4; i++) {
                int row = arow + i * 16;
                int cc  = ks * 2 + acc_k;
                LDSM4(ah[i], sb + TSZ + row * 64 + ((cc ^ ((row >> 1) & 3)) << 4));
            }
            #pragma unroll
            for (int i = 0; i < 4; i++)
                #pragma unroll
                for (int j = 0; j < 4; j++)
                    MMA16816(acc[i][j], ah[i], bh[j][0], bh[j][1]);
        }
        __syncthreads();
    }

    // ---------------- epilogue ----------------
    const int g = lane >> 2, t4 = lane & 3;
    #pragma unroll
    for (int i = 0; i < 4; i++) {
        #pragma unroll
        for (int j = 0; j < 4; j++) {
            #pragma unroll
            for (int half = 0; half < 2; half++) {
                const int m = m0 + wm + i * 16 + g + half * 8;
                const int n = n0 + wn + j * 8 + t4 * 2;
                float v0 = acc[i][j][half * 2 + 0];
                float v1 = acc[i][j][half * 2 + 1];
                if (MODE == 2) {
                    float2* dst = (float2*)(fout + (long long)bz * NN * NN +
                                            (long long)m * NN + n);
                    *dst = make_float2(v0, v1);
                } else if (MODE == 3) {
                    const long long off = (long long)bz * NN * LL + (long long)m * LL + n;
                    float2 rx = *(const float2*)(resid + off);
                    *(float2*)(fout + off) = make_float2(v0 + rx.x, v1 + rx.y);
                } else if (MODE == 1) {
                    const int b = m >> 11, ii = m & (NN - 1);
                    float a0 = v0 + bias[n], a1 = v1 + bias[n + 1];
                    long long i0 = (((long long)(b * LL + n)) << 11) + ii;
                    long long i1 = (((long long)(b * LL + n + 1)) << 11) + ii;
                    split_store(a0, o0, o1, i0);
                    split_store(a1, o0, o1, i1);
                } else {
                    #pragma unroll
                    for (int e = 0; e < 2; e++) {
                        int nn = n + e;
                        float val = (e ? v1 : v0) + bias[nn];
                        if (nn < HH)
                            split_store(val, o0, o1, (long long)m * KQK + nn);
                        else if (nn < 2 * HH)
                            split_store(val, o2, o3, (long long)m * KQK + (nn - HH));
                    }
                }
            }
        }
    }
}

// ---------------- host side ----------------
extern "C" void kernel_launch(void* const* d_in, const int* in_sizes, int n_in,
                              void* d_out, int out_size) {
    const float* x  = (const float*)d_in[0];
    const float* Wq = (const float*)d_in[1];
    const float* bq = (const float*)d_in[2];
    const float* Wk = (const float*)d_in[3];
    const float* bk = (const float*)d_in[4];
    const float* Wv = (const float*)d_in[5];
    const float* bv = (const float*)d_in[6];
    float* out = (float*)d_out;

    __nv_bfloat16 *xh, *xl, *wqkh, *wqkl, *wvh, *wvl, *qh, *ql, *kh, *kl, *ath, *atl, *vth, *vtl;
    float *e, *bqk;
    cudaGetSymbolAddress((void**)&xh, g_xh);     cudaGetSymbolAddress((void**)&xl, g_xl);
    cudaGetSymbolAddress((void**)&wqkh, g_wqkh); cudaGetSymbolAddress((void**)&wqkl, g_wqkl);
    cudaGetSymbolAddress((void**)&wvh, g_wvh);   cudaGetSymbolAddress((void**)&wvl, g_wvl);
    cudaGetSymbolAddress((void**)&qh, g_qh);     cudaGetSymbolAddress((void**)&ql, g_ql);
    cudaGetSymbolAddress((void**)&kh, g_kh);     cudaGetSymbolAddress((void**)&kl, g_kl);
    cudaGetSymbolAddress((void**)&e, g_e);
    cudaGetSymbolAddress((void**)&ath, g_ath);   cudaGetSymbolAddress((void**)&atl, g_atl);
    cudaGetSymbolAddress((void**)&vth, g_vth);   cudaGetSymbolAddress((void**)&vtl, g_vtl);
    cudaGetSymbolAddress((void**)&bqk, g_bqk);

    constexpr int SMEM = 3 * 4 * 128 * 32 * 2;  // 98304
    static bool attr_done = false;
    if (!attr_done) {
        cudaFuncSetAttribute(gemm_mma<0>, cudaFuncAttributeMaxDynamicSharedMemorySize, SMEM);
        cudaFuncSetAttribute(gemm_mma<1>, cudaFuncAttributeMaxDynamicSharedMemorySize, SMEM);
        cudaFuncSetAttribute(gemm_mma<2>, cudaFuncAttributeMaxDynamicSharedMemorySize, SMEM);
        cudaFuncSetAttribute(gemm_mma<3>, cudaFuncAttributeMaxDynamicSharedMemorySize, SMEM);
        attr_done = true;
    }

    {
        long long n = (long long)MTOT * LL;
        split_kernel<<<(unsigned)(n / 4 / 256), 256>>>(x, xh, xl, n);
    }
    build_wqk_kernel<<<(NWQK * LL + 255) / 256, 256>>>(Wq, bq, Wk, bk, wqkh, wqkl, bqk);
    {
        long long n = (long long)LL * LL;
        split_kernel<<<(unsigned)((n / 4 + 255) / 256), 256>>>(Wv, wvh, wvl, n);
    }
    size_t qkb = (size_t)MTOT * KQK * sizeof(__nv_bfloat16);
    cudaMemsetAsync(qh, 0, qkb); cudaMemsetAsync(ql, 0, qkb);
    cudaMemsetAsync(kh, 0, qkb); cudaMemsetAsync(kl, 0, qkb);

    gemm_mma<0><<<dim3(NWQK / 128, MTOT / 128, 1), 256, SMEM>>>(
        xh, xl, LL, 0, wqkh, wqkl, LL, 0,
        nullptr, bqk, nullptr, qh, ql, kh, kl, LL);

    gemm_mma<1><<<dim3(LL / 128, MTOT / 128, 1), 256, SMEM>>>(
        xh, xl, LL, 0, wvh, wvl, LL, 0,
        nullptr, bv, nullptr, vth, vtl, nullptr, nullptr, LL);

    gemm_mma<2><<<dim3(NN / 128, NN / 128, BB), 256, SMEM>>>(
        qh, ql, KQK, (long long)NN * KQK, kh, kl, KQK, (long long)NN * KQK,
        e, nullptr, nullptr, nullptr, nullptr, nullptr, nullptr, KQK);

    softmax_split_kernel<<<MTOT, 256>>>(e, ath, atl);

    gemm_mma<3><<<dim3(LL / 128, NN / 128, BB), 256, SMEM>>>(
        ath, atl, NN, (long long)NN * NN, vth, vtl, NN, (long long)LL * NN,
        out, nullptr, x, nullptr, nullptr, nullptr, nullptr, NN);
}

// round 6
// speedup vs baseline: 6.1035x; 1.9489x over previous
#include <cuda_runtime.h>
#include <cuda_bf16.h>
#include <cuda_fp16.h>
#include <cstdint>

// ============================================================================
// BagSelfAttention: B=8, N=2048, L=1280, H=160
// Round 6: selective precision v2 — 3-term bf16 hi/lo split HMMA for q/k path
//          (projection + energy), single-term **fp16** HMMA (BK=64) for v path
//          (v-projection + attn@v). fp16 half-ulp 2^-12 vs bf16 2^-9 fixes the
//          R5 accuracy failure at identical tensor throughput.
// ============================================================================

#define BB   8
#define NN   2048
#define LL   1280
#define HH   160
#define MTOT (BB * NN)
#define KQK  192
#define NWQK 384

__device__ __align__(1024) __nv_bfloat16 g_xh [MTOT * LL];
__device__ __align__(1024) __nv_bfloat16 g_xl [MTOT * LL];
__device__ __align__(1024) __half        g_xf [MTOT * LL];     // fp16 copy of x
__device__ __align__(1024) __nv_bfloat16 g_wqkh[NWQK * LL];
__device__ __align__(1024) __nv_bfloat16 g_wqkl[NWQK * LL];
__device__ __align__(1024) __half        g_wvh [LL * LL];
__device__ __align__(1024) __nv_bfloat16 g_qh  [MTOT * KQK];
__device__ __align__(1024) __nv_bfloat16 g_ql  [MTOT * KQK];
__device__ __align__(1024) __nv_bfloat16 g_kh  [MTOT * KQK];
__device__ __align__(1024) __nv_bfloat16 g_kl  [MTOT * KQK];
__device__ __align__(1024) float         g_e   [MTOT * NN];
__device__ __align__(1024) __half        g_ath [MTOT * NN];
__device__ __align__(1024) __half        g_vth [BB * LL * NN];
__device__ __align__(1024) float         g_bqk [NWQK];

__device__ __forceinline__ uint32_t smem_u32(const void* p) {
    uint32_t a;
    asm("{ .reg .u64 t; cvta.to.shared.u64 t, %1; cvt.u32.u64 %0, t; }"
        : "=r"(a) : "l"(p));
    return a;
}

#define CPA(dst, src) \
    asm volatile("cp.async.cg.shared.global [%0], [%1], 16;" :: "r"(dst), "l"(src) : "memory")
#define CPCOMMIT() asm volatile("cp.async.commit_group;" ::: "memory")
#define CPWAIT1()  asm volatile("cp.async.wait_group 1;" ::: "memory")

#define LDSM4(R, A) \
    asm volatile("ldmatrix.sync.aligned.m8n8.x4.shared.b16 {%0,%1,%2,%3}, [%4];" \
                 : "=r"((R)[0]), "=r"((R)[1]), "=r"((R)[2]), "=r"((R)[3]) : "r"(A))

#define MMA_BF16(C, A, B0, B1) \
    asm volatile("mma.sync.aligned.m16n8k16.row.col.f32.bf16.bf16.f32 " \
                 "{%0,%1,%2,%3}, {%4,%5,%6,%7}, {%8,%9}, {%0,%1,%2,%3};" \
                 : "+f"((C)[0]), "+f"((C)[1]), "+f"((C)[2]), "+f"((C)[3]) \
                 : "r"((A)[0]), "r"((A)[1]), "r"((A)[2]), "r"((A)[3]), "r"(B0), "r"(B1))

#define MMA_F16(C, A, B0, B1) \
    asm volatile("mma.sync.aligned.m16n8k16.row.col.f32.f16.f16.f32 " \
                 "{%0,%1,%2,%3}, {%4,%5,%6,%7}, {%8,%9}, {%0,%1,%2,%3};" \
                 : "+f"((C)[0]), "+f"((C)[1]), "+f"((C)[2]), "+f"((C)[3]) \
                 : "r"((A)[0]), "r"((A)[1]), "r"((A)[2]), "r"((A)[3]), "r"(B0), "r"(B1))

__device__ __forceinline__ void split_store(float v, __nv_bfloat16* h, __nv_bfloat16* l,
                                            long long idx) {
    __nv_bfloat16 hi = __float2bfloat16(v);
    h[idx] = hi;
    l[idx] = __float2bfloat16(v - __bfloat162float(hi));
}

// ---------------- conversion kernels ----------------
// x -> bf16 hi/lo (for qk path) AND fp16 (for v path) in one pass
__global__ void split3_kernel(const float* __restrict__ x,
                              __nv_bfloat16* __restrict__ h,
                              __nv_bfloat16* __restrict__ l,
                              __half* __restrict__ f, long long n) {
    long long i = ((long long)blockIdx.x * blockDim.x + threadIdx.x) * 4;
    if (i >= n) return;
    float4 v = *(const float4*)(x + i);
    __nv_bfloat162 h0, h1, l0, l1;
    h0.x = __float2bfloat16(v.x); l0.x = __float2bfloat16(v.x - __bfloat162float(h0.x));
    h0.y = __float2bfloat16(v.y); l0.y = __float2bfloat16(v.y - __bfloat162float(h0.y));
    h1.x = __float2bfloat16(v.z); l1.x = __float2bfloat16(v.z - __bfloat162float(h1.x));
    h1.y = __float2bfloat16(v.w); l1.y = __float2bfloat16(v.w - __bfloat162float(h1.y));
    *(__nv_bfloat162*)(h + i) = h0; *(__nv_bfloat162*)(h + i + 2) = h1;
    *(__nv_bfloat162*)(l + i) = l0; *(__nv_bfloat162*)(l + i + 2) = l1;
    __half2 f0, f1;
    f0.x = __float2half(v.x); f0.y = __float2half(v.y);
    f1.x = __float2half(v.z); f1.y = __float2half(v.w);
    *(__half2*)(f + i) = f0; *(__half2*)(f + i + 2) = f1;
}

__global__ void tohalf_kernel(const float* __restrict__ x,
                              __half* __restrict__ h, long long n) {
    long long i = ((long long)blockIdx.x * blockDim.x + threadIdx.x) * 4;
    if (i >= n) return;
    float4 v = *(const float4*)(x + i);
    __half2 h0, h1;
    h0.x = __float2half(v.x); h0.y = __float2half(v.y);
    h1.x = __float2half(v.z); h1.y = __float2half(v.w);
    *(__half2*)(h + i) = h0; *(__half2*)(h + i + 2) = h1;
}

__global__ void build_wqk_kernel(const float* __restrict__ Wq, const float* __restrict__ bq,
                                 const float* __restrict__ Wk, const float* __restrict__ bk,
                                 __nv_bfloat16* __restrict__ wh, __nv_bfloat16* __restrict__ wl,
                                 float* __restrict__ bqk) {
    long long i = (long long)blockIdx.x * blockDim.x + threadIdx.x;
    if (i >= (long long)NWQK * LL) return;
    int r = (int)(i / LL), c = (int)(i % LL);
    float v = (r < HH) ? Wq[r * LL + c] : (r < 2 * HH) ? Wk[(r - HH) * LL + c] : 0.f;
    split_store(v, wh, wl, i);
    if (c == 0) bqk[r] = (r < HH) ? bq[r] : (r < 2 * HH) ? bk[r - HH] : 0.f;
}

// ---------------- softmax (fp32 in, fp16 out) ----------------
__global__ __launch_bounds__(256)
void softmax_f16_kernel(const float* __restrict__ E, __half* __restrict__ ah) {
    const long long row = blockIdx.x;
    const float* p = E + row * NN;
    const int tid = threadIdx.x;

    float4 v0 = *(const float4*)(p + tid * 4);
    float4 v1 = *(const float4*)(p + 1024 + tid * 4);

    float m = fmaxf(fmaxf(fmaxf(v0.x, v0.y), fmaxf(v0.z, v0.w)),
                    fmaxf(fmaxf(v1.x, v1.y), fmaxf(v1.z, v1.w)));
    #pragma unroll
    for (int o = 16; o > 0; o >>= 1) m = fmaxf(m, __shfl_xor_sync(0xffffffffu, m, o));

    __shared__ float rmax[8], rsum[8];
    if ((tid & 31) == 0) rmax[tid >> 5] = m;
    __syncthreads();
    float rowmax = rmax[0];
    #pragma unroll
    for (int i = 1; i < 8; i++) rowmax = fmaxf(rowmax, rmax[i]);

    v0.x = __expf(v0.x - rowmax); v0.y = __expf(v0.y - rowmax);
    v0.z = __expf(v0.z - rowmax); v0.w = __expf(v0.w - rowmax);
    v1.x = __expf(v1.x - rowmax); v1.y = __expf(v1.y - rowmax);
    v1.z = __expf(v1.z - rowmax); v1.w = __expf(v1.w - rowmax);

    float s = v0.x + v0.y + v0.z + v0.w + v1.x + v1.y + v1.z + v1.w;
    #pragma unroll
    for (int o = 16; o > 0; o >>= 1) s += __shfl_xor_sync(0xffffffffu, s, o);
    if ((tid & 31) == 0) rsum[tid >> 5] = s;
    __syncthreads();
    float tot = 0.f;
    #pragma unroll
    for (int i = 0; i < 8; i++) tot += rsum[i];

    const float inv = 1.f / tot;
    long long base = row * NN;
    __half2 o0, o1;
    o0.x = __float2half(v0.x * inv); o0.y = __float2half(v0.y * inv);
    o1.x = __float2half(v0.z * inv); o1.y = __float2half(v0.w * inv);
    *(__half2*)(ah + base + tid * 4) = o0;
    *(__half2*)(ah + base + tid * 4 + 2) = o1;
    o0.x = __float2half(v1.x * inv); o0.y = __float2half(v1.y * inv);
    o1.x = __float2half(v1.z * inv); o1.y = __float2half(v1.w * inv);
    *(__half2*)(ah + base + 1024 + tid * 4) = o0;
    *(__half2*)(ah + base + 1024 + tid * 4 + 2) = o1;
}

// ---------------- HMMA GEMM ----------------
// TERMS=3: bf16 hi/lo 3-term split, BKT=32.  TERMS=1: fp16 single, BKT=64.
// MODE 0: qk-proj (bias, split-write q/k)  MODE 1: v-proj (bias, fp16 vT write)
// MODE 2: energy (fp32 store)              MODE 3: attn@v (residual, fp32 store)
template <int MODE, int TERMS, int BKT>
__global__ __launch_bounds__(256, 2)
void gemm_mma(const void* __restrict__ Ah_, const void* __restrict__ Al_,
              int lda, long long sA,
              const void* __restrict__ Bh_, const void* __restrict__ Bl_,
              int ldb, long long sB,
              float* __restrict__ fout, const float* __restrict__ bias,
              const float* __restrict__ resid,
              void* __restrict__ o0v, __nv_bfloat16* __restrict__ o1,
              __nv_bfloat16* __restrict__ o2, __nv_bfloat16* __restrict__ o3,
              int K)
{
    extern __shared__ char smem[];
    constexpr int ROWB = BKT * 2;
    constexpr int TSZ  = 128 * ROWB;
    constexpr int NTILE = (TERMS == 3) ? 4 : 2;
    constexpr int SSZ  = NTILE * TSZ;
    constexpr int BOFF = (TERMS == 3) ? 2 * TSZ : TSZ;
    const uint32_t sb0 = smem_u32(smem);

    const int tid = threadIdx.x, lane = tid & 31, wid = tid >> 5;
    const int bz = blockIdx.z;
    const int m0 = blockIdx.y * 128;
    const int n0 = blockIdx.x * 128;

    const uint16_t* Ah = (const uint16_t*)Ah_ + bz * sA;
    const uint16_t* Bh = (const uint16_t*)Bh_ + bz * sB;
    const uint16_t* Al = (TERMS == 3) ? (const uint16_t*)Al_ + bz * sA : nullptr;
    const uint16_t* Bl = (TERMS == 3) ? (const uint16_t*)Bl_ + bz * sB : nullptr;

    auto swz = [](int row, int ch) -> uint32_t {
        if (BKT == 32) return (uint32_t)(row * 64 + ((ch ^ ((row >> 1) & 3)) << 4));
        else           return (uint32_t)(row * 128 + ((ch ^ (row & 7)) << 4));
    };

    auto load_stage = [&](int kt, int s) {
        const uint32_t sb = sb0 + (uint32_t)s * SSZ;
        const int k0 = kt * BKT;
        if (TERMS == 3) {
            #pragma unroll
            for (int i = 0; i < 2; i++) {
                int c = tid + i * 256;
                int row = c >> 2, ch = c & 3;
                uint32_t off = swz(row, ch);
                CPA(sb + off,            Ah + (long long)(m0 + row) * lda + k0 + ch * 8);
                CPA(sb + TSZ + off,      Al + (long long)(m0 + row) * lda + k0 + ch * 8);
                CPA(sb + 2 * TSZ + off,  Bh + (long long)(n0 + row) * ldb + k0 + ch * 8);
                CPA(sb + 3 * TSZ + off,  Bl + (long long)(n0 + row) * ldb + k0 + ch * 8);
            }
        } else {
            #pragma unroll
            for (int i = 0; i < 4; i++) {
                int c = tid + i * 256;
                int row = c >> 3, ch = c & 7;
                uint32_t off = swz(row, ch);
                CPA(sb + off,       Ah + (long long)(m0 + row) * lda + k0 + ch * 8);
                CPA(sb + TSZ + off, Bh + (long long)(n0 + row) * ldb + k0 + ch * 8);
            }
        }
        CPCOMMIT();
    };

    const int nk = K / BKT;
    load_stage(0, 0);
    load_stage(1, 1);

    const int wm = (wid >> 2) * 64;
    const int wn = (wid & 3) * 32;

    float acc[4][4][4];
    #pragma unroll
    for (int i = 0; i < 4; i++)
        #pragma unroll
        for (int j = 0; j < 4; j++)
            #pragma unroll
            for (int r = 0; r < 4; r++) acc[i][j][r] = 0.f;

    const int arow = wm + (lane & 7) + (lane & 8);
    const int brow = wn + (lane & 7) + ((lane & 16) >> 1);
    const int acc_k = (lane >> 4);
    const int bcc_k = ((lane >> 3) & 1);

    for (int t = 0; t < nk; t++) {
        const int s = t % 3;
        CPWAIT1();
        __syncthreads();
        if (t + 2 < nk) load_stage(t + 2, (t + 2) % 3);
        else CPCOMMIT();

        const uint32_t sb = sb0 + (uint32_t)s * SSZ;
        #pragma unroll
        for (int ks = 0; ks < BKT / 16; ks++) {
            uint32_t ah[4][4];
            #pragma unroll
            for (int i = 0; i < 4; i++) {
                int row = arow + i * 16;
                int cc  = ks * 2 + acc_k;
                LDSM4(ah[i], sb + swz(row, cc));
            }
            uint32_t bh[4][2];
            #pragma unroll
            for (int j2 = 0; j2 < 2; j2++) {
                int row = brow + j2 * 16;
                int cc  = ks * 2 + bcc_k;
                uint32_t r[4];
                LDSM4(r, sb + BOFF + swz(row, cc));
                bh[2 * j2][0] = r[0]; bh[2 * j2][1] = r[1];
                bh[2 * j2 + 1][0] = r[2]; bh[2 * j2 + 1][1] = r[3];
            }
            #pragma unroll
            for (int i = 0; i < 4; i++)
                #pragma unroll
                for (int j = 0; j < 4; j++) {
                    if (TERMS == 3) MMA_BF16(acc[i][j], ah[i], bh[j][0], bh[j][1]);
                    else            MMA_F16 (acc[i][j], ah[i], bh[j][0], bh[j][1]);
                }

            if (TERMS == 3) {
                {
                    uint32_t bl[4][2];
                    #pragma unroll
                    for (int j2 = 0; j2 < 2; j2++) {
                        int row = brow + j2 * 16;
                        int cc  = ks * 2 + bcc_k;
                        uint32_t r[4];
                        LDSM4(r, sb + 3 * TSZ + swz(row, cc));
                        bl[2 * j2][0] = r[0]; bl[2 * j2][1] = r[1];
                        bl[2 * j2 + 1][0] = r[2]; bl[2 * j2 + 1][1] = r[3];
                    }
                    #pragma unroll
                    for (int i = 0; i < 4; i++)
                        #pragma unroll
                        for (int j = 0; j < 4; j++)
                            MMA_BF16(acc[i][j], ah[i], bl[j][0], bl[j][1]);
                }
                #pragma unroll
                for (int i = 0; i < 4; i++) {
                    int row = arow + i * 16;
                    int cc  = ks * 2 + acc_k;
                    LDSM4(ah[i], sb + TSZ + swz(row, cc));
                }
                #pragma unroll
                for (int i = 0; i < 4; i++)
                    #pragma unroll
                    for (int j = 0; j < 4; j++)
                        MMA_BF16(acc[i][j], ah[i], bh[j][0], bh[j][1]);
            }
        }
        __syncthreads();
    }

    // ---------------- epilogue ----------------
    const int g = lane >> 2, t4 = lane & 3;
    #pragma unroll
    for (int i = 0; i < 4; i++) {
        #pragma unroll
        for (int j = 0; j < 4; j++) {
            #pragma unroll
            for (int half = 0; half < 2; half++) {
                const int m = m0 + wm + i * 16 + g + half * 8;
                const int n = n0 + wn + j * 8 + t4 * 2;
                float v0 = acc[i][j][half * 2 + 0];
                float v1 = acc[i][j][half * 2 + 1];
                if (MODE == 2) {
                    float2* dst = (float2*)(fout + (long long)bz * NN * NN +
                                            (long long)m * NN + n);
                    *dst = make_float2(v0, v1);
                } else if (MODE == 3) {
                    const long long off = (long long)bz * NN * LL + (long long)m * LL + n;
                    float2 rx = *(const float2*)(resid + off);
                    *(float2*)(fout + off) = make_float2(v0 + rx.x, v1 + rx.y);
                } else if (MODE == 1) {
                    __half* oh = (__half*)o0v;
                    const int b = m >> 11, ii = m & (NN - 1);
                    long long i0 = (((long long)(b * LL + n)) << 11) + ii;
                    long long i1 = (((long long)(b * LL + n + 1)) << 11) + ii;
                    oh[i0] = __float2half(v0 + bias[n]);
                    oh[i1] = __float2half(v1 + bias[n + 1]);
                } else {
                    __nv_bfloat16* oq = (__nv_bfloat16*)o0v;
                    #pragma unroll
                    for (int e = 0; e < 2; e++) {
                        int nn = n + e;
                        float val = (e ? v1 : v0) + bias[nn];
                        if (nn < HH)
                            split_store(val, oq, o1, (long long)m * KQK + nn);
                        else if (nn < 2 * HH)
                            split_store(val, o2, o3, (long long)m * KQK + (nn - HH));
                    }
                }
            }
        }
    }
}

// ---------------- host side ----------------
extern "C" void kernel_launch(void* const* d_in, const int* in_sizes, int n_in,
                              void* d_out, int out_size) {
    const float* x  = (const float*)d_in[0];
    const float* Wq = (const float*)d_in[1];
    const float* bq = (const float*)d_in[2];
    const float* Wk = (const float*)d_in[3];
    const float* bk = (const float*)d_in[4];
    const float* Wv = (const float*)d_in[5];
    const float* bv = (const float*)d_in[6];
    float* out = (float*)d_out;

    __nv_bfloat16 *xh, *xl, *wqkh, *wqkl, *qh, *ql, *kh, *kl;
    __half *xf, *wvh, *ath, *vth;
    float *e, *bqk;
    cudaGetSymbolAddress((void**)&xh, g_xh);     cudaGetSymbolAddress((void**)&xl, g_xl);
    cudaGetSymbolAddress((void**)&xf, g_xf);
    cudaGetSymbolAddress((void**)&wqkh, g_wqkh); cudaGetSymbolAddress((void**)&wqkl, g_wqkl);
    cudaGetSymbolAddress((void**)&wvh, g_wvh);
    cudaGetSymbolAddress((void**)&qh, g_qh);     cudaGetSymbolAddress((void**)&ql, g_ql);
    cudaGetSymbolAddress((void**)&kh, g_kh);     cudaGetSymbolAddress((void**)&kl, g_kl);
    cudaGetSymbolAddress((void**)&e, g_e);
    cudaGetSymbolAddress((void**)&ath, g_ath);
    cudaGetSymbolAddress((void**)&vth, g_vth);
    cudaGetSymbolAddress((void**)&bqk, g_bqk);

    constexpr int SMEM = 3 * 4 * 128 * 32 * 2;  // 98304
    static bool attr_done = false;
    if (!attr_done) {
        cudaFuncSetAttribute((const void*)gemm_mma<0, 3, 32>,
                             cudaFuncAttributeMaxDynamicSharedMemorySize, SMEM);
        cudaFuncSetAttribute((const void*)gemm_mma<1, 1, 64>,
                             cudaFuncAttributeMaxDynamicSharedMemorySize, SMEM);
        cudaFuncSetAttribute((const void*)gemm_mma<2, 3, 32>,
                             cudaFuncAttributeMaxDynamicSharedMemorySize, SMEM);
        cudaFuncSetAttribute((const void*)gemm_mma<3, 1, 64>,
                             cudaFuncAttributeMaxDynamicSharedMemorySize, SMEM);
        attr_done = true;
    }

    {
        long long n = (long long)MTOT * LL;
        split3_kernel<<<(unsigned)(n / 4 / 256), 256>>>(x, xh, xl, xf, n);
    }
    build_wqk_kernel<<<(NWQK * LL + 255) / 256, 256>>>(Wq, bq, Wk, bk, wqkh, wqkl, bqk);
    {
        long long n = (long long)LL * LL;
        tohalf_kernel<<<(unsigned)((n / 4 + 255) / 256), 256>>>(Wv, wvh, n);
    }
    size_t qkb = (size_t)MTOT * KQK * sizeof(__nv_bfloat16);
    cudaMemsetAsync(qh, 0, qkb); cudaMemsetAsync(ql, 0, qkb);
    cudaMemsetAsync(kh, 0, qkb); cudaMemsetAsync(kl, 0, qkb);

    // qk projection (3-term bf16): [16384, 384] = x @ Wqk^T, split-write q/k
    gemm_mma<0, 3, 32><<<dim3(NWQK / 128, MTOT / 128, 1), 256, SMEM>>>(
        xh, xl, LL, 0, wqkh, wqkl, LL, 0,
        nullptr, bqk, nullptr, qh, ql, kh, kl, LL);

    // v projection (fp16 single): [16384, 1280] = x @ Wv^T -> vT fp16
    gemm_mma<1, 1, 64><<<dim3(LL / 128, MTOT / 128, 1), 256, SMEM>>>(
        xf, nullptr, LL, 0, wvh, nullptr, LL, 0,
        nullptr, bv, nullptr, vth, nullptr, nullptr, nullptr, LL);

    // energy (3-term bf16): per batch E = q @ k^T (K = 192 padded)
    gemm_mma<2, 3, 32><<<dim3(NN / 128, NN / 128, BB), 256, SMEM>>>(
        qh, ql, KQK, (long long)NN * KQK, kh, kl, KQK, (long long)NN * KQK,
        e, nullptr, nullptr, nullptr, nullptr, nullptr, nullptr, KQK);

    // softmax -> fp16 attention weights
    softmax_f16_kernel<<<MTOT, 256>>>(e, ath);

    // attn @ v + residual (fp16 single, K = 2048)
    gemm_mma<3, 1, 64><<<dim3(LL / 128, NN / 128, BB), 256, SMEM>>>(
        ath, nullptr, NN, (long long)NN * NN, vth, nullptr, NN, (long long)LL * NN,
        out, nullptr, x, nullptr, nullptr, nullptr, nullptr, NN);
}

// round 7
// speedup vs baseline: 6.1394x; 1.0059x over previous
#include <cuda_runtime.h>
#include <cuda_bf16.h>
#include <cuda_fp16.h>
#include <cstdint>

// ============================================================================
// BagSelfAttention: B=8, N=2048, L=1280, H=160
// Round 7: merged projection launch (qk 3-term bf16 + v fp16 in ONE grid to
//          kill wave-quantization tail + serialization), single __syncthreads
//          per k-iter. Energy 3-term bf16; attn@v fp16; fp32 softmax.
// ============================================================================

#define BB   8
#define NN   2048
#define LL   1280
#define HH   160
#define MTOT (BB * NN)
#define KQK  192
#define NWQK 384

__device__ __align__(1024) __nv_bfloat16 g_xh [MTOT * LL];
__device__ __align__(1024) __nv_bfloat16 g_xl [MTOT * LL];
__device__ __align__(1024) __half        g_xf [MTOT * LL];
__device__ __align__(1024) __nv_bfloat16 g_wqkh[NWQK * LL];
__device__ __align__(1024) __nv_bfloat16 g_wqkl[NWQK * LL];
__device__ __align__(1024) __half        g_wvh [LL * LL];
__device__ __align__(1024) __nv_bfloat16 g_qh  [MTOT * KQK];
__device__ __align__(1024) __nv_bfloat16 g_ql  [MTOT * KQK];
__device__ __align__(1024) __nv_bfloat16 g_kh  [MTOT * KQK];
__device__ __align__(1024) __nv_bfloat16 g_kl  [MTOT * KQK];
__device__ __align__(1024) float         g_e   [MTOT * NN];
__device__ __align__(1024) __half        g_ath [MTOT * NN];
__device__ __align__(1024) __half        g_vth [BB * LL * NN];
__device__ __align__(1024) float         g_bqk [NWQK];

__device__ __forceinline__ uint32_t smem_u32(const void* p) {
    uint32_t a;
    asm("{ .reg .u64 t; cvta.to.shared.u64 t, %1; cvt.u32.u64 %0, t; }"
        : "=r"(a) : "l"(p));
    return a;
}

#define CPA(dst, src) \
    asm volatile("cp.async.cg.shared.global [%0], [%1], 16;" :: "r"(dst), "l"(src) : "memory")
#define CPCOMMIT() asm volatile("cp.async.commit_group;" ::: "memory")
#define CPWAIT1()  asm volatile("cp.async.wait_group 1;" ::: "memory")

#define LDSM4(R, A) \
    asm volatile("ldmatrix.sync.aligned.m8n8.x4.shared.b16 {%0,%1,%2,%3}, [%4];" \
                 : "=r"((R)[0]), "=r"((R)[1]), "=r"((R)[2]), "=r"((R)[3]) : "r"(A))

#define MMA_BF16(C, A, B0, B1) \
    asm volatile("mma.sync.aligned.m16n8k16.row.col.f32.bf16.bf16.f32 " \
                 "{%0,%1,%2,%3}, {%4,%5,%6,%7}, {%8,%9}, {%0,%1,%2,%3};" \
                 : "+f"((C)[0]), "+f"((C)[1]), "+f"((C)[2]), "+f"((C)[3]) \
                 : "r"((A)[0]), "r"((A)[1]), "r"((A)[2]), "r"((A)[3]), "r"(B0), "r"(B1))

#define MMA_F16(C, A, B0, B1) \
    asm volatile("mma.sync.aligned.m16n8k16.row.col.f32.f16.f16.f32 " \
                 "{%0,%1,%2,%3}, {%4,%5,%6,%7}, {%8,%9}, {%0,%1,%2,%3};" \
                 : "+f"((C)[0]), "+f"((C)[1]), "+f"((C)[2]), "+f"((C)[3]) \
                 : "r"((A)[0]), "r"((A)[1]), "r"((A)[2]), "r"((A)[3]), "r"(B0), "r"(B1))

__device__ __forceinline__ void split_store(float v, __nv_bfloat16* h, __nv_bfloat16* l,
                                            long long idx) {
    __nv_bfloat16 hi = __float2bfloat16(v);
    h[idx] = hi;
    l[idx] = __float2bfloat16(v - __bfloat162float(hi));
}

// ---------------- conversion kernels ----------------
__global__ void split3_kernel(const float* __restrict__ x,
                              __nv_bfloat16* __restrict__ h,
                              __nv_bfloat16* __restrict__ l,
                              __half* __restrict__ f, long long n) {
    long long i = ((long long)blockIdx.x * blockDim.x + threadIdx.x) * 4;
    if (i >= n) return;
    float4 v = *(const float4*)(x + i);
    __nv_bfloat162 h0, h1, l0, l1;
    h0.x = __float2bfloat16(v.x); l0.x = __float2bfloat16(v.x - __bfloat162float(h0.x));
    h0.y = __float2bfloat16(v.y); l0.y = __float2bfloat16(v.y - __bfloat162float(h0.y));
    h1.x = __float2bfloat16(v.z); l1.x = __float2bfloat16(v.z - __bfloat162float(h1.x));
    h1.y = __float2bfloat16(v.w); l1.y = __float2bfloat16(v.w - __bfloat162float(h1.y));
    *(__nv_bfloat162*)(h + i) = h0; *(__nv_bfloat162*)(h + i + 2) = h1;
    *(__nv_bfloat162*)(l + i) = l0; *(__nv_bfloat162*)(l + i + 2) = l1;
    __half2 f0, f1;
    f0.x = __float2half(v.x); f0.y = __float2half(v.y);
    f1.x = __float2half(v.z); f1.y = __float2half(v.w);
    *(__half2*)(f + i) = f0; *(__half2*)(f + i + 2) = f1;
}

__global__ void tohalf_kernel(const float* __restrict__ x,
                              __half* __restrict__ h, long long n) {
    long long i = ((long long)blockIdx.x * blockDim.x + threadIdx.x) * 4;
    if (i >= n) return;
    float4 v = *(const float4*)(x + i);
    __half2 h0, h1;
    h0.x = __float2half(v.x); h0.y = __float2half(v.y);
    h1.x = __float2half(v.z); h1.y = __float2half(v.w);
    *(__half2*)(h + i) = h0; *(__half2*)(h + i + 2) = h1;
}

__global__ void build_wqk_kernel(const float* __restrict__ Wq, const float* __restrict__ bq,
                                 const float* __restrict__ Wk, const float* __restrict__ bk,
                                 __nv_bfloat16* __restrict__ wh, __nv_bfloat16* __restrict__ wl,
                                 float* __restrict__ bqk) {
    long long i = (long long)blockIdx.x * blockDim.x + threadIdx.x;
    if (i >= (long long)NWQK * LL) return;
    int r = (int)(i / LL), c = (int)(i % LL);
    float v = (r < HH) ? Wq[r * LL + c] : (r < 2 * HH) ? Wk[(r - HH) * LL + c] : 0.f;
    split_store(v, wh, wl, i);
    if (c == 0) bqk[r] = (r < HH) ? bq[r] : (r < 2 * HH) ? bk[r - HH] : 0.f;
}

// ---------------- softmax (fp32 in, fp16 out) ----------------
__global__ __launch_bounds__(256)
void softmax_f16_kernel(const float* __restrict__ E, __half* __restrict__ ah) {
    const long long row = blockIdx.x;
    const float* p = E + row * NN;
    const int tid = threadIdx.x;

    float4 v0 = *(const float4*)(p + tid * 4);
    float4 v1 = *(const float4*)(p + 1024 + tid * 4);

    float m = fmaxf(fmaxf(fmaxf(v0.x, v0.y), fmaxf(v0.z, v0.w)),
                    fmaxf(fmaxf(v1.x, v1.y), fmaxf(v1.z, v1.w)));
    #pragma unroll
    for (int o = 16; o > 0; o >>= 1) m = fmaxf(m, __shfl_xor_sync(0xffffffffu, m, o));

    __shared__ float rmax[8], rsum[8];
    if ((tid & 31) == 0) rmax[tid >> 5] = m;
    __syncthreads();
    float rowmax = rmax[0];
    #pragma unroll
    for (int i = 1; i < 8; i++) rowmax = fmaxf(rowmax, rmax[i]);

    v0.x = __expf(v0.x - rowmax); v0.y = __expf(v0.y - rowmax);
    v0.z = __expf(v0.z - rowmax); v0.w = __expf(v0.w - rowmax);
    v1.x = __expf(v1.x - rowmax); v1.y = __expf(v1.y - rowmax);
    v1.z = __expf(v1.z - rowmax); v1.w = __expf(v1.w - rowmax);

    float s = v0.x + v0.y + v0.z + v0.w + v1.x + v1.y + v1.z + v1.w;
    #pragma unroll
    for (int o = 16; o > 0; o >>= 1) s += __shfl_xor_sync(0xffffffffu, s, o);
    if ((tid & 31) == 0) rsum[tid >> 5] = s;
    __syncthreads();
    float tot = 0.f;
    #pragma unroll
    for (int i = 0; i < 8; i++) tot += rsum[i];

    const float inv = 1.f / tot;
    long long base = row * NN;
    __half2 o0, o1;
    o0.x = __float2half(v0.x * inv); o0.y = __float2half(v0.y * inv);
    o1.x = __float2half(v0.z * inv); o1.y = __float2half(v0.w * inv);
    *(__half2*)(ah + base + tid * 4) = o0;
    *(__half2*)(ah + base + tid * 4 + 2) = o1;
    o0.x = __float2half(v1.x * inv); o0.y = __float2half(v1.y * inv);
    o1.x = __float2half(v1.z * inv); o1.y = __float2half(v1.w * inv);
    *(__half2*)(ah + base + 1024 + tid * 4) = o0;
    *(__half2*)(ah + base + 1024 + tid * 4 + 2) = o1;
}

// ---------------- GEMM body (device function) ----------------
// TERMS=3: bf16 hi/lo 3-term split, BKT=32.  TERMS=1: fp16 single, BKT=64.
// MODE 0: qk-proj (bias, split-write q/k)  MODE 1: v-proj (bias, fp16 vT write)
// MODE 2: energy (fp32 store)              MODE 3: attn@v (residual, fp32 store)
template <int MODE, int TERMS, int BKT>
__device__ __forceinline__
void gemm_body(char* smem, int m0, int n0, int bz,
               const uint16_t* __restrict__ Ah, const uint16_t* __restrict__ Al,
               int lda, long long sA,
               const uint16_t* __restrict__ Bh, const uint16_t* __restrict__ Bl,
               int ldb, long long sB,
               float* __restrict__ fout, const float* __restrict__ bias,
               const float* __restrict__ resid,
               void* __restrict__ o0v, __nv_bfloat16* __restrict__ o1,
               __nv_bfloat16* __restrict__ o2, __nv_bfloat16* __restrict__ o3,
               int K)
{
    constexpr int ROWB = BKT * 2;
    constexpr int TSZ  = 128 * ROWB;
    constexpr int NTILE = (TERMS == 3) ? 4 : 2;
    constexpr int SSZ  = NTILE * TSZ;
    constexpr int BOFF = (TERMS == 3) ? 2 * TSZ : TSZ;
    const uint32_t sb0 = smem_u32(smem);

    const int tid = threadIdx.x, lane = tid & 31, wid = tid >> 5;

    Ah += bz * sA; Bh += bz * sB;
    if (TERMS == 3) { Al += bz * sA; Bl += bz * sB; }

    auto swz = [](int row, int ch) -> uint32_t {
        if (BKT == 32) return (uint32_t)(row * 64 + ((ch ^ ((row >> 1) & 3)) << 4));
        else           return (uint32_t)(row * 128 + ((ch ^ (row & 7)) << 4));
    };

    auto load_stage = [&](int kt, int s) {
        const uint32_t sb = sb0 + (uint32_t)s * SSZ;
        const int k0 = kt * BKT;
        if (TERMS == 3) {
            #pragma unroll
            for (int i = 0; i < 2; i++) {
                int c = tid + i * 256;
                int row = c >> 2, ch = c & 3;
                uint32_t off = swz(row, ch);
                CPA(sb + off,            Ah + (long long)(m0 + row) * lda + k0 + ch * 8);
                CPA(sb + TSZ + off,      Al + (long long)(m0 + row) * lda + k0 + ch * 8);
                CPA(sb + 2 * TSZ + off,  Bh + (long long)(n0 + row) * ldb + k0 + ch * 8);
                CPA(sb + 3 * TSZ + off,  Bl + (long long)(n0 + row) * ldb + k0 + ch * 8);
            }
        } else {
            #pragma unroll
            for (int i = 0; i < 4; i++) {
                int c = tid + i * 256;
                int row = c >> 3, ch = c & 7;
                uint32_t off = swz(row, ch);
                CPA(sb + off,       Ah + (long long)(m0 + row) * lda + k0 + ch * 8);
                CPA(sb + TSZ + off, Bh + (long long)(n0 + row) * ldb + k0 + ch * 8);
            }
        }
        CPCOMMIT();
    };

    const int nk = K / BKT;
    load_stage(0, 0);
    load_stage(1, 1);

    const int wm = (wid >> 2) * 64;
    const int wn = (wid & 3) * 32;

    float acc[4][4][4];
    #pragma unroll
    for (int i = 0; i < 4; i++)
        #pragma unroll
        for (int j = 0; j < 4; j++)
            #pragma unroll
            for (int r = 0; r < 4; r++) acc[i][j][r] = 0.f;

    const int arow = wm + (lane & 7) + (lane & 8);
    const int brow = wn + (lane & 7) + ((lane & 16) >> 1);
    const int acc_k = (lane >> 4);
    const int bcc_k = ((lane >> 3) & 1);

    for (int t = 0; t < nk; t++) {
        const int s = t % 3;
        CPWAIT1();
        // Single barrier per iteration: orders (a) this stage's data ready for
        // all warps, and (b) all warps' reads of the stage that prefetch below
        // will overwrite (it was last read in the previous iteration).
        __syncthreads();
        if (t + 2 < nk) load_stage(t + 2, (t + 2) % 3);
        else CPCOMMIT();

        const uint32_t sb = sb0 + (uint32_t)s * SSZ;
        #pragma unroll
        for (int ks = 0; ks < BKT / 16; ks++) {
            uint32_t ah[4][4];
            #pragma unroll
            for (int i = 0; i < 4; i++) {
                int row = arow + i * 16;
                int cc  = ks * 2 + acc_k;
                LDSM4(ah[i], sb + swz(row, cc));
            }
            uint32_t bh[4][2];
            #pragma unroll
            for (int j2 = 0; j2 < 2; j2++) {
                int row = brow + j2 * 16;
                int cc  = ks * 2 + bcc_k;
                uint32_t r[4];
                LDSM4(r, sb + BOFF + swz(row, cc));
                bh[2 * j2][0] = r[0]; bh[2 * j2][1] = r[1];
                bh[2 * j2 + 1][0] = r[2]; bh[2 * j2 + 1][1] = r[3];
            }
            #pragma unroll
            for (int i = 0; i < 4; i++)
                #pragma unroll
                for (int j = 0; j < 4; j++) {
                    if (TERMS == 3) MMA_BF16(acc[i][j], ah[i], bh[j][0], bh[j][1]);
                    else            MMA_F16 (acc[i][j], ah[i], bh[j][0], bh[j][1]);
                }

            if (TERMS == 3) {
                {
                    uint32_t bl[4][2];
                    #pragma unroll
                    for (int j2 = 0; j2 < 2; j2++) {
                        int row = brow + j2 * 16;
                        int cc  = ks * 2 + bcc_k;
                        uint32_t r[4];
                        LDSM4(r, sb + 3 * TSZ + swz(row, cc));
                        bl[2 * j2][0] = r[0]; bl[2 * j2][1] = r[1];
                        bl[2 * j2 + 1][0] = r[2]; bl[2 * j2 + 1][1] = r[3];
                    }
                    #pragma unroll
                    for (int i = 0; i < 4; i++)
                        #pragma unroll
                        for (int j = 0; j < 4; j++)
                            MMA_BF16(acc[i][j], ah[i], bl[j][0], bl[j][1]);
                }
                #pragma unroll
                for (int i = 0; i < 4; i++) {
                    int row = arow + i * 16;
                    int cc  = ks * 2 + acc_k;
                    LDSM4(ah[i], sb + TSZ + swz(row, cc));
                }
                #pragma unroll
                for (int i = 0; i < 4; i++)
                    #pragma unroll
                    for (int j = 0; j < 4; j++)
                        MMA_BF16(acc[i][j], ah[i], bh[j][0], bh[j][1]);
            }
        }
    }

    // ---------------- epilogue ----------------
    const int g = lane >> 2, t4 = lane & 3;
    #pragma unroll
    for (int i = 0; i < 4; i++) {
        #pragma unroll
        for (int j = 0; j < 4; j++) {
            #pragma unroll
            for (int half = 0; half < 2; half++) {
                const int m = m0 + wm + i * 16 + g + half * 8;
                const int n = n0 + wn + j * 8 + t4 * 2;
                float v0 = acc[i][j][half * 2 + 0];
                float v1 = acc[i][j][half * 2 + 1];
                if (MODE == 2) {
                    float2* dst = (float2*)(fout + (long long)bz * NN * NN +
                                            (long long)m * NN + n);
                    *dst = make_float2(v0, v1);
                } else if (MODE == 3) {
                    const long long off = (long long)bz * NN * LL + (long long)m * LL + n;
                    float2 rx = *(const float2*)(resid + off);
                    *(float2*)(fout + off) = make_float2(v0 + rx.x, v1 + rx.y);
                } else if (MODE == 1) {
                    __half* oh = (__half*)o0v;
                    const int b = m >> 11, ii = m & (NN - 1);
                    long long i0 = (((long long)(b * LL + n)) << 11) + ii;
                    long long i1 = (((long long)(b * LL + n + 1)) << 11) + ii;
                    oh[i0] = __float2half(v0 + bias[n]);
                    oh[i1] = __float2half(v1 + bias[n + 1]);
                } else {
                    __nv_bfloat16* oq = (__nv_bfloat16*)o0v;
                    #pragma unroll
                    for (int e = 0; e < 2; e++) {
                        int nn = n + e;
                        float val = (e ? v1 : v0) + bias[nn];
                        if (nn < HH)
                            split_store(val, oq, o1, (long long)m * KQK + nn);
                        else if (nn < 2 * HH)
                            split_store(val, o2, o3, (long long)m * KQK + (nn - HH));
                    }
                }
            }
        }
    }
}

// ---------------- merged projection kernel ----------------
// grid (13, 128): bx in [0,3) -> qk-proj 3-term tiles; bx in [3,13) -> v-proj
// fp16 tiles. One launch = no serialization, tail amortized over 1664 CTAs.
__global__ __launch_bounds__(256, 2)
void proj_merged(const __nv_bfloat16* __restrict__ xh, const __nv_bfloat16* __restrict__ xl,
                 const __half* __restrict__ xf,
                 const __nv_bfloat16* __restrict__ wqkh, const __nv_bfloat16* __restrict__ wqkl,
                 const __half* __restrict__ wvh,
                 const float* __restrict__ bqk, const float* __restrict__ bv,
                 __nv_bfloat16* __restrict__ qh, __nv_bfloat16* __restrict__ ql,
                 __nv_bfloat16* __restrict__ kh, __nv_bfloat16* __restrict__ kl,
                 __half* __restrict__ vth)
{
    extern __shared__ char smem[];
    const int bx = blockIdx.x;
    const int m0 = blockIdx.y * 128;
    if (bx < 3) {
        gemm_body<0, 3, 32>(smem, m0, bx * 128, 0,
                            (const uint16_t*)xh, (const uint16_t*)xl, LL, 0,
                            (const uint16_t*)wqkh, (const uint16_t*)wqkl, LL, 0,
                            nullptr, bqk, nullptr, qh, ql, kh, kl, LL);
    } else {
        gemm_body<1, 1, 64>(smem, m0, (bx - 3) * 128, 0,
                            (const uint16_t*)xf, nullptr, LL, 0,
                            (const uint16_t*)wvh, nullptr, LL, 0,
                            nullptr, bv, nullptr, vth, nullptr, nullptr, nullptr, LL);
    }
}

__global__ __launch_bounds__(256, 2)
void energy_kernel(const __nv_bfloat16* __restrict__ qh, const __nv_bfloat16* __restrict__ ql,
                   const __nv_bfloat16* __restrict__ kh, const __nv_bfloat16* __restrict__ kl,
                   float* __restrict__ e)
{
    extern __shared__ char smem[];
    gemm_body<2, 3, 32>(smem, blockIdx.y * 128, blockIdx.x * 128, blockIdx.z,
                        (const uint16_t*)qh, (const uint16_t*)ql, KQK, (long long)NN * KQK,
                        (const uint16_t*)kh, (const uint16_t*)kl, KQK, (long long)NN * KQK,
                        e, nullptr, nullptr, nullptr, nullptr, nullptr, nullptr, KQK);
}

__global__ __launch_bounds__(256, 2)
void attnv_kernel(const __half* __restrict__ ath, const __half* __restrict__ vth,
                  const float* __restrict__ x, float* __restrict__ out)
{
    extern __shared__ char smem[];
    gemm_body<3, 1, 64>(smem, blockIdx.y * 128, blockIdx.x * 128, blockIdx.z,
                        (const uint16_t*)ath, nullptr, NN, (long long)NN * NN,
                        (const uint16_t*)vth, nullptr, NN, (long long)LL * NN,
                        out, nullptr, x, nullptr, nullptr, nullptr, nullptr, NN);
}

// ---------------- host side ----------------
extern "C" void kernel_launch(void* const* d_in, const int* in_sizes, int n_in,
                              void* d_out, int out_size) {
    const float* x  = (const float*)d_in[0];
    const float* Wq = (const float*)d_in[1];
    const float* bq = (const float*)d_in[2];
    const float* Wk = (const float*)d_in[3];
    const float* bk = (const float*)d_in[4];
    const float* Wv = (const float*)d_in[5];
    const float* bv = (const float*)d_in[6];
    float* out = (float*)d_out;

    __nv_bfloat16 *xh, *xl, *wqkh, *wqkl, *qh, *ql, *kh, *kl;
    __half *xf, *wvh, *ath, *vth;
    float *e, *bqk;
    cudaGetSymbolAddress((void**)&xh, g_xh);     cudaGetSymbolAddress((void**)&xl, g_xl);
    cudaGetSymbolAddress((void**)&xf, g_xf);
    cudaGetSymbolAddress((void**)&wqkh, g_wqkh); cudaGetSymbolAddress((void**)&wqkl, g_wqkl);
    cudaGetSymbolAddress((void**)&wvh, g_wvh);
    cudaGetSymbolAddress((void**)&qh, g_qh);     cudaGetSymbolAddress((void**)&ql, g_ql);
    cudaGetSymbolAddress((void**)&kh, g_kh);     cudaGetSymbolAddress((void**)&kl, g_kl);
    cudaGetSymbolAddress((void**)&e, g_e);
    cudaGetSymbolAddress((void**)&ath, g_ath);
    cudaGetSymbolAddress((void**)&vth, g_vth);
    cudaGetSymbolAddress((void**)&bqk, g_bqk);

    constexpr int SMEM = 3 * 4 * 128 * 32 * 2;  // 98304
    static bool attr_done = false;
    if (!attr_done) {
        cudaFuncSetAttribute((const void*)proj_merged,
                             cudaFuncAttributeMaxDynamicSharedMemorySize, SMEM);
        cudaFuncSetAttribute((const void*)energy_kernel,
                             cudaFuncAttributeMaxDynamicSharedMemorySize, SMEM);
        cudaFuncSetAttribute((const void*)attnv_kernel,
                             cudaFuncAttributeMaxDynamicSharedMemorySize, SMEM);
        attr_done = true;
    }

    {
        long long n = (long long)MTOT * LL;
        split3_kernel<<<(unsigned)(n / 4 / 256), 256>>>(x, xh, xl, xf, n);
    }
    build_wqk_kernel<<<(NWQK * LL + 255) / 256, 256>>>(Wq, bq, Wk, bk, wqkh, wqkl, bqk);
    {
        long long n = (long long)LL * LL;
        tohalf_kernel<<<(unsigned)((n / 4 + 255) / 256), 256>>>(Wv, wvh, n);
    }
    size_t qkb = (size_t)MTOT * KQK * sizeof(__nv_bfloat16);
    cudaMemsetAsync(qh, 0, qkb); cudaMemsetAsync(ql, 0, qkb);
    cudaMemsetAsync(kh, 0, qkb); cudaMemsetAsync(kl, 0, qkb);

    // merged projections: qk (3-term) + v (fp16) in one grid
    proj_merged<<<dim3(13, MTOT / 128, 1), 256, SMEM>>>(
        xh, xl, xf, wqkh, wqkl, wvh, bqk, bv, qh, ql, kh, kl, vth);

    // energy (3-term bf16): per batch E = q @ k^T (K = 192 padded)
    energy_kernel<<<dim3(NN / 128, NN / 128, BB), 256, SMEM>>>(qh, ql, kh, kl, e);

    // softmax -> fp16 attention weights
    softmax_f16_kernel<<<MTOT, 256>>>(e, ath);

    // attn @ v + residual (fp16, K = 2048)
    attnv_kernel<<<dim3(LL / 128, NN / 128, BB), 256, SMEM>>>(ath, vth, x, out);
}

// round 8
// speedup vs baseline: 6.5019x; 1.0590x over previous
#include <cuda_runtime.h>
#include <cuda_bf16.h>
#include <cuda_fp16.h>
#include <cstdint>

// ============================================================================
// BagSelfAttention: B=8, N=2048, L=1280, H=160
// Round 8: R7 structure + exact-K energy path (K=160, no padding, no memsets).
//   qk path: 3-term bf16 hi/lo split HMMA. v path: single-term fp16 HMMA.
// ============================================================================

#define BB   8
#define NN   2048
#define LL   1280
#define HH   160
#define MTOT (BB * NN)
#define KQK  160             // exact H — 5 k-iters of 32
#define NWQK 384             // stacked Wq|Wk padded to 3 n-tiles (pad cols discarded)

__device__ __align__(1024) __nv_bfloat16 g_xh [MTOT * LL];
__device__ __align__(1024) __nv_bfloat16 g_xl [MTOT * LL];
__device__ __align__(1024) __half        g_xf [MTOT * LL];
__device__ __align__(1024) __nv_bfloat16 g_wqkh[NWQK * LL];
__device__ __align__(1024) __nv_bfloat16 g_wqkl[NWQK * LL];
__device__ __align__(1024) __half        g_wvh [LL * LL];
__device__ __align__(1024) __nv_bfloat16 g_qh  [MTOT * KQK];
__device__ __align__(1024) __nv_bfloat16 g_ql  [MTOT * KQK];
__device__ __align__(1024) __nv_bfloat16 g_kh  [MTOT * KQK];
__device__ __align__(1024) __nv_bfloat16 g_kl  [MTOT * KQK];
__device__ __align__(1024) float         g_e   [MTOT * NN];
__device__ __align__(1024) __half        g_ath [MTOT * NN];
__device__ __align__(1024) __half        g_vth [BB * LL * NN];
__device__ __align__(1024) float         g_bqk [NWQK];

__device__ __forceinline__ uint32_t smem_u32(const void* p) {
    uint32_t a;
    asm("{ .reg .u64 t; cvta.to.shared.u64 t, %1; cvt.u32.u64 %0, t; }"
        : "=r"(a) : "l"(p));
    return a;
}

#define CPA(dst, src) \
    asm volatile("cp.async.cg.shared.global [%0], [%1], 16;" :: "r"(dst), "l"(src) : "memory")
#define CPCOMMIT() asm volatile("cp.async.commit_group;" ::: "memory")
#define CPWAIT1()  asm volatile("cp.async.wait_group 1;" ::: "memory")

#define LDSM4(R, A) \
    asm volatile("ldmatrix.sync.aligned.m8n8.x4.shared.b16 {%0,%1,%2,%3}, [%4];" \
                 : "=r"((R)[0]), "=r"((R)[1]), "=r"((R)[2]), "=r"((R)[3]) : "r"(A))

#define MMA_BF16(C, A, B0, B1) \
    asm volatile("mma.sync.aligned.m16n8k16.row.col.f32.bf16.bf16.f32 " \
                 "{%0,%1,%2,%3}, {%4,%5,%6,%7}, {%8,%9}, {%0,%1,%2,%3};" \
                 : "+f"((C)[0]), "+f"((C)[1]), "+f"((C)[2]), "+f"((C)[3]) \
                 : "r"((A)[0]), "r"((A)[1]), "r"((A)[2]), "r"((A)[3]), "r"(B0), "r"(B1))

#define MMA_F16(C, A, B0, B1) \
    asm volatile("mma.sync.aligned.m16n8k16.row.col.f32.f16.f16.f32 " \
                 "{%0,%1,%2,%3}, {%4,%5,%6,%7}, {%8,%9}, {%0,%1,%2,%3};" \
                 : "+f"((C)[0]), "+f"((C)[1]), "+f"((C)[2]), "+f"((C)[3]) \
                 : "r"((A)[0]), "r"((A)[1]), "r"((A)[2]), "r"((A)[3]), "r"(B0), "r"(B1))

__device__ __forceinline__ void split_store(float v, __nv_bfloat16* h, __nv_bfloat16* l,
                                            long long idx) {
    __nv_bfloat16 hi = __float2bfloat16(v);
    h[idx] = hi;
    l[idx] = __float2bfloat16(v - __bfloat162float(hi));
}

// ---------------- conversion kernels ----------------
__global__ void split3_kernel(const float* __restrict__ x,
                              __nv_bfloat16* __restrict__ h,
                              __nv_bfloat16* __restrict__ l,
                              __half* __restrict__ f, long long n) {
    long long i = ((long long)blockIdx.x * blockDim.x + threadIdx.x) * 4;
    if (i >= n) return;
    float4 v = *(const float4*)(x + i);
    __nv_bfloat162 h0, h1, l0, l1;
    h0.x = __float2bfloat16(v.x); l0.x = __float2bfloat16(v.x - __bfloat162float(h0.x));
    h0.y = __float2bfloat16(v.y); l0.y = __float2bfloat16(v.y - __bfloat162float(h0.y));
    h1.x = __float2bfloat16(v.z); l1.x = __float2bfloat16(v.z - __bfloat162float(h1.x));
    h1.y = __float2bfloat16(v.w); l1.y = __float2bfloat16(v.w - __bfloat162float(h1.y));
    *(__nv_bfloat162*)(h + i) = h0; *(__nv_bfloat162*)(h + i + 2) = h1;
    *(__nv_bfloat162*)(l + i) = l0; *(__nv_bfloat162*)(l + i + 2) = l1;
    __half2 f0, f1;
    f0.x = __float2half(v.x); f0.y = __float2half(v.y);
    f1.x = __float2half(v.z); f1.y = __float2half(v.w);
    *(__half2*)(f + i) = f0; *(__half2*)(f + i + 2) = f1;
}

__global__ void tohalf_kernel(const float* __restrict__ x,
                              __half* __restrict__ h, long long n) {
    long long i = ((long long)blockIdx.x * blockDim.x + threadIdx.x) * 4;
    if (i >= n) return;
    float4 v = *(const float4*)(x + i);
    __half2 h0, h1;
    h0.x = __float2half(v.x); h0.y = __float2half(v.y);
    h1.x = __float2half(v.z); h1.y = __float2half(v.w);
    *(__half2*)(h + i) = h0; *(__half2*)(h + i + 2) = h1;
}

__global__ void build_wqk_kernel(const float* __restrict__ Wq, const float* __restrict__ bq,
                                 const float* __restrict__ Wk, const float* __restrict__ bk,
                                 __nv_bfloat16* __restrict__ wh, __nv_bfloat16* __restrict__ wl,
                                 float* __restrict__ bqk) {
    long long i = (long long)blockIdx.x * blockDim.x + threadIdx.x;
    if (i >= (long long)NWQK * LL) return;
    int r = (int)(i / LL), c = (int)(i % LL);
    float v = (r < HH) ? Wq[r * LL + c] : (r < 2 * HH) ? Wk[(r - HH) * LL + c] : 0.f;
    split_store(v, wh, wl, i);
    if (c == 0) bqk[r] = (r < HH) ? bq[r] : (r < 2 * HH) ? bk[r - HH] : 0.f;
}

// ---------------- softmax (fp32 in, fp16 out) ----------------
__global__ __launch_bounds__(256)
void softmax_f16_kernel(const float* __restrict__ E, __half* __restrict__ ah) {
    const long long row = blockIdx.x;
    const float* p = E + row * NN;
    const int tid = threadIdx.x;

    float4 v0 = *(const float4*)(p + tid * 4);
    float4 v1 = *(const float4*)(p + 1024 + tid * 4);

    float m = fmaxf(fmaxf(fmaxf(v0.x, v0.y), fmaxf(v0.z, v0.w)),
                    fmaxf(fmaxf(v1.x, v1.y), fmaxf(v1.z, v1.w)));
    #pragma unroll
    for (int o = 16; o > 0; o >>= 1) m = fmaxf(m, __shfl_xor_sync(0xffffffffu, m, o));

    __shared__ float rmax[8], rsum[8];
    if ((tid & 31) == 0) rmax[tid >> 5] = m;
    __syncthreads();
    float rowmax = rmax[0];
    #pragma unroll
    for (int i = 1; i < 8; i++) rowmax = fmaxf(rowmax, rmax[i]);

    v0.x = __expf(v0.x - rowmax); v0.y = __expf(v0.y - rowmax);
    v0.z = __expf(v0.z - rowmax); v0.w = __expf(v0.w - rowmax);
    v1.x = __expf(v1.x - rowmax); v1.y = __expf(v1.y - rowmax);
    v1.z = __expf(v1.z - rowmax); v1.w = __expf(v1.w - rowmax);

    float s = v0.x + v0.y + v0.z + v0.w + v1.x + v1.y + v1.z + v1.w;
    #pragma unroll
    for (int o = 16; o > 0; o >>= 1) s += __shfl_xor_sync(0xffffffffu, s, o);
    if ((tid & 31) == 0) rsum[tid >> 5] = s;
    __syncthreads();
    float tot = 0.f;
    #pragma unroll
    for (int i = 0; i < 8; i++) tot += rsum[i];

    const float inv = 1.f / tot;
    long long base = row * NN;
    __half2 o0, o1;
    o0.x = __float2half(v0.x * inv); o0.y = __float2half(v0.y * inv);
    o1.x = __float2half(v0.z * inv); o1.y = __float2half(v0.w * inv);
    *(__half2*)(ah + base + tid * 4) = o0;
    *(__half2*)(ah + base + tid * 4 + 2) = o1;
    o0.x = __float2half(v1.x * inv); o0.y = __float2half(v1.y * inv);
    o1.x = __float2half(v1.z * inv); o1.y = __float2half(v1.w * inv);
    *(__half2*)(ah + base + 1024 + tid * 4) = o0;
    *(__half2*)(ah + base + 1024 + tid * 4 + 2) = o1;
}

// ---------------- GEMM body ----------------
// TERMS=3: bf16 hi/lo 3-term split, BKT=32.  TERMS=1: fp16 single, BKT=64.
// MODE 0: qk-proj (bias, split-write q/k)  MODE 1: v-proj (bias, fp16 vT write)
// MODE 2: energy (fp32 store)              MODE 3: attn@v (residual, fp32 store)
template <int MODE, int TERMS, int BKT>
__device__ __forceinline__
void gemm_body(char* smem, int m0, int n0, int bz,
               const uint16_t* __restrict__ Ah, const uint16_t* __restrict__ Al,
               int lda, long long sA,
               const uint16_t* __restrict__ Bh, const uint16_t* __restrict__ Bl,
               int ldb, long long sB,
               float* __restrict__ fout, const float* __restrict__ bias,
               const float* __restrict__ resid,
               void* __restrict__ o0v, __nv_bfloat16* __restrict__ o1,
               __nv_bfloat16* __restrict__ o2, __nv_bfloat16* __restrict__ o3,
               int K)
{
    constexpr int ROWB = BKT * 2;
    constexpr int TSZ  = 128 * ROWB;
    constexpr int NTILE = (TERMS == 3) ? 4 : 2;
    constexpr int SSZ  = NTILE * TSZ;
    constexpr int BOFF = (TERMS == 3) ? 2 * TSZ : TSZ;
    const uint32_t sb0 = smem_u32(smem);

    const int tid = threadIdx.x, lane = tid & 31, wid = tid >> 5;

    Ah += bz * sA; Bh += bz * sB;
    if (TERMS == 3) { Al += bz * sA; Bl += bz * sB; }

    auto swz = [](int row, int ch) -> uint32_t {
        if (BKT == 32) return (uint32_t)(row * 64 + ((ch ^ ((row >> 1) & 3)) << 4));
        else           return (uint32_t)(row * 128 + ((ch ^ (row & 7)) << 4));
    };

    auto load_stage = [&](int kt, int s) {
        const uint32_t sb = sb0 + (uint32_t)s * SSZ;
        const int k0 = kt * BKT;
        if (TERMS == 3) {
            #pragma unroll
            for (int i = 0; i < 2; i++) {
                int c = tid + i * 256;
                int row = c >> 2, ch = c & 3;
                uint32_t off = swz(row, ch);
                CPA(sb + off,            Ah + (long long)(m0 + row) * lda + k0 + ch * 8);
                CPA(sb + TSZ + off,      Al + (long long)(m0 + row) * lda + k0 + ch * 8);
                CPA(sb + 2 * TSZ + off,  Bh + (long long)(n0 + row) * ldb + k0 + ch * 8);
                CPA(sb + 3 * TSZ + off,  Bl + (long long)(n0 + row) * ldb + k0 + ch * 8);
            }
        } else {
            #pragma unroll
            for (int i = 0; i < 4; i++) {
                int c = tid + i * 256;
                int row = c >> 3, ch = c & 7;
                uint32_t off = swz(row, ch);
                CPA(sb + off,       Ah + (long long)(m0 + row) * lda + k0 + ch * 8);
                CPA(sb + TSZ + off, Bh + (long long)(n0 + row) * ldb + k0 + ch * 8);
            }
        }
        CPCOMMIT();
    };

    const int nk = K / BKT;
    load_stage(0, 0);
    load_stage(1, 1);

    const int wm = (wid >> 2) * 64;
    const int wn = (wid & 3) * 32;

    float acc[4][4][4];
    #pragma unroll
    for (int i = 0; i < 4; i++)
        #pragma unroll
        for (int j = 0; j < 4; j++)
            #pragma unroll
            for (int r = 0; r < 4; r++) acc[i][j][r] = 0.f;

    const int arow = wm + (lane & 7) + (lane & 8);
    const int brow = wn + (lane & 7) + ((lane & 16) >> 1);
    const int acc_k = (lane >> 4);
    const int bcc_k = ((lane >> 3) & 1);

    for (int t = 0; t < nk; t++) {
        const int s = t % 3;
        CPWAIT1();
        __syncthreads();
        if (t + 2 < nk) load_stage(t + 2, (t + 2) % 3);
        else CPCOMMIT();

        const uint32_t sb = sb0 + (uint32_t)s * SSZ;
        #pragma unroll
        for (int ks = 0; ks < BKT / 16; ks++) {
            uint32_t ah[4][4];
            #pragma unroll
            for (int i = 0; i < 4; i++) {
                int row = arow + i * 16;
                int cc  = ks * 2 + acc_k;
                LDSM4(ah[i], sb + swz(row, cc));
            }
            uint32_t bh[4][2];
            #pragma unroll
            for (int j2 = 0; j2 < 2; j2++) {
                int row = brow + j2 * 16;
                int cc  = ks * 2 + bcc_k;
                uint32_t r[4];
                LDSM4(r, sb + BOFF + swz(row, cc));
                bh[2 * j2][0] = r[0]; bh[2 * j2][1] = r[1];
                bh[2 * j2 + 1][0] = r[2]; bh[2 * j2 + 1][1] = r[3];
            }
            #pragma unroll
            for (int i = 0; i < 4; i++)
                #pragma unroll
                for (int j = 0; j < 4; j++) {
                    if (TERMS == 3) MMA_BF16(acc[i][j], ah[i], bh[j][0], bh[j][1]);
                    else            MMA_F16 (acc[i][j], ah[i], bh[j][0], bh[j][1]);
                }

            if (TERMS == 3) {
                {
                    uint32_t bl[4][2];
                    #pragma unroll
                    for (int j2 = 0; j2 < 2; j2++) {
                        int row = brow + j2 * 16;
                        int cc  = ks * 2 + bcc_k;
                        uint32_t r[4];
                        LDSM4(r, sb + 3 * TSZ + swz(row, cc));
                        bl[2 * j2][0] = r[0]; bl[2 * j2][1] = r[1];
                        bl[2 * j2 + 1][0] = r[2]; bl[2 * j2 + 1][1] = r[3];
                    }
                    #pragma unroll
                    for (int i = 0; i < 4; i++)
                        #pragma unroll
                        for (int j = 0; j < 4; j++)
                            MMA_BF16(acc[i][j], ah[i], bl[j][0], bl[j][1]);
                }
                #pragma unroll
                for (int i = 0; i < 4; i++) {
                    int row = arow + i * 16;
                    int cc  = ks * 2 + acc_k;
                    LDSM4(ah[i], sb + TSZ + swz(row, cc));
                }
                #pragma unroll
                for (int i = 0; i < 4; i++)
                    #pragma unroll
                    for (int j = 0; j < 4; j++)
                        MMA_BF16(acc[i][j], ah[i], bh[j][0], bh[j][1]);
            }
        }
    }

    // ---------------- epilogue ----------------
    const int g = lane >> 2, t4 = lane & 3;
    #pragma unroll
    for (int i = 0; i < 4; i++) {
        #pragma unroll
        for (int j = 0; j < 4; j++) {
            #pragma unroll
            for (int half = 0; half < 2; half++) {
                const int m = m0 + wm + i * 16 + g + half * 8;
                const int n = n0 + wn + j * 8 + t4 * 2;
                float v0 = acc[i][j][half * 2 + 0];
                float v1 = acc[i][j][half * 2 + 1];
                if (MODE == 2) {
                    float2* dst = (float2*)(fout + (long long)bz * NN * NN +
                                            (long long)m * NN + n);
                    *dst = make_float2(v0, v1);
                } else if (MODE == 3) {
                    const long long off = (long long)bz * NN * LL + (long long)m * LL + n;
                    float2 rx = *(const float2*)(resid + off);
                    *(float2*)(fout + off) = make_float2(v0 + rx.x, v1 + rx.y);
                } else if (MODE == 1) {
                    __half* oh = (__half*)o0v;
                    const int b = m >> 11, ii = m & (NN - 1);
                    long long i0 = (((long long)(b * LL + n)) << 11) + ii;
                    long long i1 = (((long long)(b * LL + n + 1)) << 11) + ii;
                    oh[i0] = __float2half(v0 + bias[n]);
                    oh[i1] = __float2half(v1 + bias[n + 1]);
                } else {
                    __nv_bfloat16* oq = (__nv_bfloat16*)o0v;
                    #pragma unroll
                    for (int e = 0; e < 2; e++) {
                        int nn = n + e;
                        float val = (e ? v1 : v0) + bias[nn];
                        if (nn < HH)
                            split_store(val, oq, o1, (long long)m * KQK + nn);
                        else if (nn < 2 * HH)
                            split_store(val, o2, o3, (long long)m * KQK + (nn - HH));
                    }
                }
            }
        }
    }
}

// ---------------- merged projection kernel ----------------
__global__ __launch_bounds__(256, 2)
void proj_merged(const __nv_bfloat16* __restrict__ xh, const __nv_bfloat16* __restrict__ xl,
                 const __half* __restrict__ xf,
                 const __nv_bfloat16* __restrict__ wqkh, const __nv_bfloat16* __restrict__ wqkl,
                 const __half* __restrict__ wvh,
                 const float* __restrict__ bqk, const float* __restrict__ bv,
                 __nv_bfloat16* __restrict__ qh, __nv_bfloat16* __restrict__ ql,
                 __nv_bfloat16* __restrict__ kh, __nv_bfloat16* __restrict__ kl,
                 __half* __restrict__ vth)
{
    extern __shared__ char smem[];
    const int bx = blockIdx.x;
    const int m0 = blockIdx.y * 128;
    if (bx < 3) {
        gemm_body<0, 3, 32>(smem, m0, bx * 128, 0,
                            (const uint16_t*)xh, (const uint16_t*)xl, LL, 0,
                            (const uint16_t*)wqkh, (const uint16_t*)wqkl, LL, 0,
                            nullptr, bqk, nullptr, qh, ql, kh, kl, LL);
    } else {
        gemm_body<1, 1, 64>(smem, m0, (bx - 3) * 128, 0,
                            (const uint16_t*)xf, nullptr, LL, 0,
                            (const uint16_t*)wvh, nullptr, LL, 0,
                            nullptr, bv, nullptr, vth, nullptr, nullptr, nullptr, LL);
    }
}

__global__ __launch_bounds__(256, 2)
void energy_kernel(const __nv_bfloat16* __restrict__ qh, const __nv_bfloat16* __restrict__ ql,
                   const __nv_bfloat16* __restrict__ kh, const __nv_bfloat16* __restrict__ kl,
                   float* __restrict__ e)
{
    extern __shared__ char smem[];
    gemm_body<2, 3, 32>(smem, blockIdx.y * 128, blockIdx.x * 128, blockIdx.z,
                        (const uint16_t*)qh, (const uint16_t*)ql, KQK, (long long)NN * KQK,
                        (const uint16_t*)kh, (const uint16_t*)kl, KQK, (long long)NN * KQK,
                        e, nullptr, nullptr, nullptr, nullptr, nullptr, nullptr, KQK);
}

__global__ __launch_bounds__(256, 2)
void attnv_kernel(const __half* __restrict__ ath, const __half* __restrict__ vth,
                  const float* __restrict__ x, float* __restrict__ out)
{
    extern __shared__ char smem[];
    gemm_body<3, 1, 64>(smem, blockIdx.y * 128, blockIdx.x * 128, blockIdx.z,
                        (const uint16_t*)ath, nullptr, NN, (long long)NN * NN,
                        (const uint16_t*)vth, nullptr, NN, (long long)LL * NN,
                        out, nullptr, x, nullptr, nullptr, nullptr, nullptr, NN);
}

// ---------------- host side ----------------
extern "C" void kernel_launch(void* const* d_in, const int* in_sizes, int n_in,
                              void* d_out, int out_size) {
    const float* x  = (const float*)d_in[0];
    const float* Wq = (const float*)d_in[1];
    const float* bq = (const float*)d_in[2];
    const float* Wk = (const float*)d_in[3];
    const float* bk = (const float*)d_in[4];
    const float* Wv = (const float*)d_in[5];
    const float* bv = (const float*)d_in[6];
    float* out = (float*)d_out;

    __nv_bfloat16 *xh, *xl, *wqkh, *wqkl, *qh, *ql, *kh, *kl;
    __half *xf, *wvh, *ath, *vth;
    float *e, *bqk;
    cudaGetSymbolAddress((void**)&xh, g_xh);     cudaGetSymbolAddress((void**)&xl, g_xl);
    cudaGetSymbolAddress((void**)&xf, g_xf);
    cudaGetSymbolAddress((void**)&wqkh, g_wqkh); cudaGetSymbolAddress((void**)&wqkl, g_wqkl);
    cudaGetSymbolAddress((void**)&wvh, g_wvh);
    cudaGetSymbolAddress((void**)&qh, g_qh);     cudaGetSymbolAddress((void**)&ql, g_ql);
    cudaGetSymbolAddress((void**)&kh, g_kh);     cudaGetSymbolAddress((void**)&kl, g_kl);
    cudaGetSymbolAddress((void**)&e, g_e);
    cudaGetSymbolAddress((void**)&ath, g_ath);
    cudaGetSymbolAddress((void**)&vth, g_vth);
    cudaGetSymbolAddress((void**)&bqk, g_bqk);

    constexpr int SMEM = 3 * 4 * 128 * 32 * 2;  // 98304
    static bool attr_done = false;
    if (!attr_done) {
        cudaFuncSetAttribute((const void*)proj_merged,
                             cudaFuncAttributeMaxDynamicSharedMemorySize, SMEM);
        cudaFuncSetAttribute((const void*)energy_kernel,
                             cudaFuncAttributeMaxDynamicSharedMemorySize, SMEM);
        cudaFuncSetAttribute((const void*)attnv_kernel,
                             cudaFuncAttributeMaxDynamicSharedMemorySize, SMEM);
        attr_done = true;
    }

    {
        long long n = (long long)MTOT * LL;
        split3_kernel<<<(unsigned)(n / 4 / 256), 256>>>(x, xh, xl, xf, n);
    }
    build_wqk_kernel<<<(NWQK * LL + 255) / 256, 256>>>(Wq, bq, Wk, bk, wqkh, wqkl, bqk);
    {
        long long n = (long long)LL * LL;
        tohalf_kernel<<<(unsigned)((n / 4 + 255) / 256), 256>>>(Wv, wvh, n);
    }
    // No memsets needed: q/k buffers are exactly [MTOT, 160] and fully written
    // by the qk-proj epilogue (every n < 320 element covered).

    // merged projections: qk (3-term) + v (fp16) in one grid
    proj_merged<<<dim3(13, MTOT / 128, 1), 256, SMEM>>>(
        xh, xl, xf, wqkh, wqkl, wvh, bqk, bv, qh, ql, kh, kl, vth);

    // energy (3-term bf16): per batch E = q @ k^T, exact K = 160 (5 k-iters)
    energy_kernel<<<dim3(NN / 128, NN / 128, BB), 256, SMEM>>>(qh, ql, kh, kl, e);

    // softmax -> fp16 attention weights
    softmax_f16_kernel<<<MTOT, 256>>>(e, ath);

    // attn @ v + residual (fp16, K = 2048)
    attnv_kernel<<<dim3(LL / 128, NN / 128, BB), 256, SMEM>>>(ath, vth, x, out);
}